// round 2
// baseline (speedup 1.0000x reference)
#include <cuda_runtime.h>
#include <math.h>

#define Bb 2
#define SS 2048
#define DD 2048
#define HH 16
#define HDm 128
#define MM (Bb*SS)   // 4096

// Scratch (device globals: no allocation allowed)
__device__ float g_Q[Bb*HH*SS*HDm];   // [b,h,s,d]
__device__ float g_K[Bb*HH*SS*HDm];
__device__ float g_V[Bb*HH*SS*HDm];
__device__ float g_CTX[MM*DD];        // [b*s, h*hd]

// ---------------------------------------------------------------------------
// SGEMM: out[m,n] = sum_k A[m,k] * W[n,k]   (A row-major MxK, W row-major NxK)
// Tile 128x64, BK=16, 256 threads, 8x4 per thread.
// OUTSEL 0/1/2 -> write Q/K/V in [b,h,s,d] layout; 3 -> plain [m,n] to outp,
// reading A from g_CTX.
// ---------------------------------------------------------------------------
template<int OUTSEL>
__global__ __launch_bounds__(256) void sgemm128x64(const float* __restrict__ A,
                                                   const float* __restrict__ W,
                                                   float* __restrict__ outp)
{
    __shared__ float As[16][128];
    __shared__ float Bs[16][64];
    const int tid = threadIdx.x;
    const int bm = blockIdx.y, bn = blockIdx.x;
    const int ty = tid >> 4, tx = tid & 15;   // 16x16 thread grid
    const int arow = tid >> 1;                // 0..127
    const int akc  = (tid & 1) * 8;           // 0 or 8
    const int brow = tid >> 2;                // 0..63
    const int bkc  = (tid & 3) * 4;

    const float* Abase = (OUTSEL == 3) ? g_CTX : A;
    const float* Ap = Abase + (size_t)(bm*128 + arow)*DD + akc;
    const float* Wp = W     + (size_t)(bn*64  + brow)*DD + bkc;

    float acc[8][4];
#pragma unroll
    for (int i = 0; i < 8; i++)
#pragma unroll
        for (int j = 0; j < 4; j++) acc[i][j] = 0.f;

    for (int k0 = 0; k0 < DD; k0 += 16) {
        float4 a0 = *(const float4*)(Ap + k0);
        float4 a1 = *(const float4*)(Ap + k0 + 4);
        float4 b0 = *(const float4*)(Wp + k0);
        __syncthreads();
        As[akc+0][arow]=a0.x; As[akc+1][arow]=a0.y; As[akc+2][arow]=a0.z; As[akc+3][arow]=a0.w;
        As[akc+4][arow]=a1.x; As[akc+5][arow]=a1.y; As[akc+6][arow]=a1.z; As[akc+7][arow]=a1.w;
        Bs[bkc+0][brow]=b0.x; Bs[bkc+1][brow]=b0.y; Bs[bkc+2][brow]=b0.z; Bs[bkc+3][brow]=b0.w;
        __syncthreads();
#pragma unroll
        for (int k = 0; k < 16; k++) {
            float4 av0 = *(const float4*)&As[k][ty*8];
            float4 av1 = *(const float4*)&As[k][ty*8+4];
            float4 bv  = *(const float4*)&Bs[k][tx*4];
            float ar[8] = {av0.x,av0.y,av0.z,av0.w,av1.x,av1.y,av1.z,av1.w};
            float br[4] = {bv.x,bv.y,bv.z,bv.w};
#pragma unroll
            for (int i = 0; i < 8; i++)
#pragma unroll
                for (int j = 0; j < 4; j++)
                    acc[i][j] = fmaf(ar[i], br[j], acc[i][j]);
        }
    }

    const int c0 = bn*64 + tx*4;
#pragma unroll
    for (int i = 0; i < 8; i++) {
        const int m = bm*128 + ty*8 + i;
        float4 v = make_float4(acc[i][0], acc[i][1], acc[i][2], acc[i][3]);
        if (OUTSEL < 3) {
            float* O = (OUTSEL == 0) ? g_Q : (OUTSEL == 1) ? g_K : g_V;
            const int b = m / SS, s = m % SS;
            const int h = c0 >> 7, d = c0 & 127;
            *(float4*)&O[(((size_t)(b*HH + h))*SS + s)*HDm + d] = v;
        } else {
            *(float4*)&outp[(size_t)m*DD + c0] = v;
        }
    }
}

// ---------------------------------------------------------------------------
// RoPE on Q and K in-place. cos/sin tables are [S, HD]; table[:, d] == table[:, d+64].
// ---------------------------------------------------------------------------
__global__ __launch_bounds__(256) void rope_kernel(const float* __restrict__ cosT,
                                                   const float* __restrict__ sinT)
{
    const int idx = blockIdx.x * 256 + threadIdx.x;   // Bb*HH*SS*64 total
    const int d   = idx & 63;
    const int bhs = idx >> 6;
    const int s   = bhs & (SS - 1);
    const float c  = cosT[s*HDm + d];
    const float sn = sinT[s*HDm + d];
    const size_t base = (size_t)bhs * HDm;
    float q1 = g_Q[base + d], q2 = g_Q[base + d + 64];
    g_Q[base + d]      = q1*c - q2*sn;
    g_Q[base + d + 64] = q2*c + q1*sn;
    float k1 = g_K[base + d], k2 = g_K[base + d + 64];
    g_K[base + d]      = k1*c - k2*sn;
    g_K[base + d + 64] = k2*c + k1*sn;
}

// ---------------------------------------------------------------------------
// Flash attention (causal), fp32. 128 threads per block.
// Q tile 32 rows, K/V tiles 64 rows, HD=128.
// Thread (qg = tid/16 in 0..7, kg = tid%16):
//   scores: 4q x 4k micro-tile; PV: 4q x 8d slice. Row stats via 16-lane shfl.
// Output written directly in [b, s, h*HD+d] layout into g_CTX.
// ---------------------------------------------------------------------------
#define QT 32
#define KT 64
#define KSP 132   // padded row for Ks (bank-conflict avoidance)
#define PSP 68    // padded row for Ps
#define SM_KS 0
#define SM_VS (KT*KSP)             // 8448
#define SM_QS (SM_VS + KT*HDm)     // 16640
#define SM_PS (SM_QS + QT*HDm)     // 20736
#define SM_TOT (SM_PS + QT*PSP)    // 22912 floats = 91648 bytes

__global__ __launch_bounds__(128) void flash_kernel()
{
    extern __shared__ float sm[];
    float* Ks = sm + SM_KS;
    float* Vs = sm + SM_VS;
    float* Qs = sm + SM_QS;
    float* Ps = sm + SM_PS;

    const int tid = threadIdx.x;
    const int qg = tid >> 4;     // 0..7  -> q rows qg*4..qg*4+3
    const int kg = tid & 15;     // 0..15 -> k cols kg*4..+3 / d slice kg*8..+7
    const int bh = blockIdx.y;   // b*HH + h
    const int q0 = blockIdx.x * QT;

    const float* Qg = g_Q + (size_t)bh * SS * HDm;
    const float* Kg = g_K + (size_t)bh * SS * HDm;
    const float* Vg = g_V + (size_t)bh * SS * HDm;

    // Load Q tile (unpadded [32][128])
    for (int i = tid*4; i < QT*HDm; i += 128*4) {
        const int r = i >> 7, c = i & 127;
        *(float4*)&Qs[r*HDm + c] = *(const float4*)&Qg[(size_t)(q0 + r)*HDm + c];
    }

    float m[4], l[4], acc[4][8];
#pragma unroll
    for (int i = 0; i < 4; i++) {
        m[i] = -1e30f; l[i] = 0.f;
#pragma unroll
        for (int j = 0; j < 8; j++) acc[i][j] = 0.f;
    }

    const int ntiles = q0 / KT + 1;
    const float scale = 0.08838834764831845f;  // 1/sqrt(128)

    for (int t = 0; t < ntiles; t++) {
        const int j0 = t * KT;
        __syncthreads();   // previous iter's Vs/Ps reads done; also covers Qs load on t=0
        for (int i = tid*4; i < KT*HDm; i += 128*4) {
            const int r = i >> 7, c = i & 127;
            *(float4*)&Ks[r*KSP + c] = *(const float4*)&Kg[(size_t)(j0 + r)*HDm + c];
            *(float4*)&Vs[r*HDm + c] = *(const float4*)&Vg[(size_t)(j0 + r)*HDm + c];
        }
        __syncthreads();

        // ---- scores: 4x4 micro-tile ----
        float s4[4][4];
#pragma unroll
        for (int i = 0; i < 4; i++)
#pragma unroll
            for (int j = 0; j < 4; j++) s4[i][j] = 0.f;

#pragma unroll 4
        for (int d0 = 0; d0 < HDm; d0 += 4) {
            float4 qv[4], kv[4];
#pragma unroll
            for (int i = 0; i < 4; i++)
                qv[i] = *(const float4*)&Qs[(qg*4 + i)*HDm + d0];
#pragma unroll
            for (int j = 0; j < 4; j++)
                kv[j] = *(const float4*)&Ks[(kg*4 + j)*KSP + d0];
#pragma unroll
            for (int i = 0; i < 4; i++)
#pragma unroll
                for (int j = 0; j < 4; j++) {
                    s4[i][j] = fmaf(qv[i].x, kv[j].x, s4[i][j]);
                    s4[i][j] = fmaf(qv[i].y, kv[j].y, s4[i][j]);
                    s4[i][j] = fmaf(qv[i].z, kv[j].z, s4[i][j]);
                    s4[i][j] = fmaf(qv[i].w, kv[j].w, s4[i][j]);
                }
        }

        // ---- mask + online softmax ----
        float corr[4];
#pragma unroll
        for (int i = 0; i < 4; i++) {
            const int qi = q0 + qg*4 + i;
            float tm = -1e30f;
#pragma unroll
            for (int j = 0; j < 4; j++) {
                const int kj = j0 + kg*4 + j;
                float v = (kj <= qi) ? s4[i][j]*scale : -1e30f;
                s4[i][j] = v;
                tm = fmaxf(tm, v);
            }
#pragma unroll
            for (int off = 8; off >= 1; off >>= 1)
                tm = fmaxf(tm, __shfl_xor_sync(0xffffffffu, tm, off));
            const float mn = fmaxf(m[i], tm);
            corr[i] = __expf(m[i] - mn);
            m[i] = mn;
            float rs = 0.f;
#pragma unroll
            for (int j = 0; j < 4; j++) {
                const float p = __expf(s4[i][j] - mn);
                s4[i][j] = p;
                rs += p;
            }
#pragma unroll
            for (int off = 8; off >= 1; off >>= 1)
                rs += __shfl_xor_sync(0xffffffffu, rs, off);
            l[i] = l[i]*corr[i] + rs;
        }

        // write probs, rescale accumulators
#pragma unroll
        for (int i = 0; i < 4; i++)
            *(float4*)&Ps[(qg*4 + i)*PSP + kg*4] =
                make_float4(s4[i][0], s4[i][1], s4[i][2], s4[i][3]);
#pragma unroll
        for (int i = 0; i < 4; i++)
#pragma unroll
            for (int d = 0; d < 8; d++) acc[i][d] *= corr[i];
        __syncthreads();

        // ---- PV: each thread accumulates 4q x 8d ----
#pragma unroll 2
        for (int k = 0; k < KT; k++) {
            const float4 v0 = *(const float4*)&Vs[k*HDm + kg*8];
            const float4 v1 = *(const float4*)&Vs[k*HDm + kg*8 + 4];
#pragma unroll
            for (int i = 0; i < 4; i++) {
                const float p = Ps[(qg*4 + i)*PSP + k];
                acc[i][0] = fmaf(p, v0.x, acc[i][0]);
                acc[i][1] = fmaf(p, v0.y, acc[i][1]);
                acc[i][2] = fmaf(p, v0.z, acc[i][2]);
                acc[i][3] = fmaf(p, v0.w, acc[i][3]);
                acc[i][4] = fmaf(p, v1.x, acc[i][4]);
                acc[i][5] = fmaf(p, v1.y, acc[i][5]);
                acc[i][6] = fmaf(p, v1.z, acc[i][6]);
                acc[i][7] = fmaf(p, v1.w, acc[i][7]);
            }
        }
    }

    // ---- epilogue: ctx in [b, s, h*HD+d] ----
    const int b = bh / HH, h = bh % HH;
#pragma unroll
    for (int i = 0; i < 4; i++) {
        const float inv = 1.f / l[i];
        const int qrow = q0 + qg*4 + i;
        float* o = &g_CTX[((size_t)(b*SS + qrow))*DD + h*HDm + kg*8];
        *(float4*)(o)     = make_float4(acc[i][0]*inv, acc[i][1]*inv, acc[i][2]*inv, acc[i][3]*inv);
        *(float4*)(o + 4) = make_float4(acc[i][4]*inv, acc[i][5]*inv, acc[i][6]*inv, acc[i][7]*inv);
    }
}

// ---------------------------------------------------------------------------
extern "C" void kernel_launch(void* const* d_in, const int* in_sizes, int n_in,
                              void* d_out, int out_size)
{
    const float* x    = (const float*)d_in[0];
    const float* Wq   = (const float*)d_in[1];
    const float* Wk   = (const float*)d_in[2];
    const float* Wv   = (const float*)d_in[3];
    const float* Wo   = (const float*)d_in[4];
    const float* cosT = (const float*)d_in[5];
    const float* sinT = (const float*)d_in[6];
    float* out = (float*)d_out;

    dim3 gg(DD/64, MM/128);   // (32, 32)
    sgemm128x64<0><<<gg, 256>>>(x, Wq, nullptr);
    sgemm128x64<1><<<gg, 256>>>(x, Wk, nullptr);
    sgemm128x64<2><<<gg, 256>>>(x, Wv, nullptr);

    rope_kernel<<<(Bb*HH*SS*64)/256, 256>>>(cosT, sinT);

    cudaFuncSetAttribute(flash_kernel,
                         cudaFuncAttributeMaxDynamicSharedMemorySize,
                         SM_TOT * (int)sizeof(float));
    flash_kernel<<<dim3(SS/QT, Bb*HH), 128, SM_TOT * sizeof(float)>>>();

    sgemm128x64<3><<<gg, 256>>>(nullptr, Wo, out);
}

// round 6
// speedup vs baseline: 1.5379x; 1.5379x over previous
#include <cuda_runtime.h>
#include <cuda_bf16.h>
#include <math.h>
#include <stdint.h>

#define Bb 2
#define SS 2048
#define DD 2048
#define HH 16
#define HDm 128
#define MM (Bb*SS)   // 4096

// ---------------------------------------------------------------------------
// Device-global scratch (no allocations allowed)
// ---------------------------------------------------------------------------
__device__ float g_Q[(size_t)Bb*HH*SS*HDm];   // [b,h,s,d] fp32 (post-RoPE)
__device__ float g_K[(size_t)Bb*HH*SS*HDm];
__device__ float g_V[(size_t)Bb*HH*SS*HDm];

__device__ __align__(16) __nv_bfloat16 g_Xh[(size_t)MM*DD],  g_Xl[(size_t)MM*DD];
__device__ __align__(16) __nv_bfloat16 g_Wqh[(size_t)DD*DD], g_Wql[(size_t)DD*DD];
__device__ __align__(16) __nv_bfloat16 g_Wkh[(size_t)DD*DD], g_Wkl[(size_t)DD*DD];
__device__ __align__(16) __nv_bfloat16 g_Wvh[(size_t)DD*DD], g_Wvl[(size_t)DD*DD];
__device__ __align__(16) __nv_bfloat16 g_Woh[(size_t)DD*DD], g_Wol[(size_t)DD*DD];
__device__ __align__(16) __nv_bfloat16 g_Ch[(size_t)MM*DD],  g_Cl[(size_t)MM*DD];

// ---------------------------------------------------------------------------
// helpers (all arch-portable PTX: works on compute_103 target)
// ---------------------------------------------------------------------------
__device__ __forceinline__ uint32_t smem_u32(const void* p) {
    uint32_t a;
    asm("{ .reg .u64 t; cvta.to.shared.u64 t, %1; cvt.u32.u64 %0, t; }"
        : "=r"(a) : "l"(p));
    return a;
}

__device__ __forceinline__ void mma16816(float* c, const uint32_t* a, const uint32_t* b) {
    asm volatile(
        "mma.sync.aligned.m16n8k16.row.col.f32.bf16.bf16.f32 "
        "{%0,%1,%2,%3}, {%4,%5,%6,%7}, {%8,%9}, {%0,%1,%2,%3};"
        : "+f"(c[0]), "+f"(c[1]), "+f"(c[2]), "+f"(c[3])
        : "r"(a[0]), "r"(a[1]), "r"(a[2]), "r"(a[3]), "r"(b[0]), "r"(b[1]));
}

// ---------------------------------------------------------------------------
// fp32 -> bf16 hi/lo splitter
// ---------------------------------------------------------------------------
template<int SEL>
__global__ __launch_bounds__(256) void split_kernel(const float* __restrict__ src, int n4)
{
    const int i = blockIdx.x * 256 + threadIdx.x;
    if (i >= n4) return;
    __nv_bfloat16* hi = (SEL==0) ? g_Xh : (SEL==1) ? g_Wqh : (SEL==2) ? g_Wkh
                      : (SEL==3) ? g_Wvh : g_Woh;
    __nv_bfloat16* lo = (SEL==0) ? g_Xl : (SEL==1) ? g_Wql : (SEL==2) ? g_Wkl
                      : (SEL==3) ? g_Wvl : g_Wol;
    const float4 v = ((const float4*)src)[i];
    __nv_bfloat162 h0, h1, l0, l1;
    h0.x = __float2bfloat16(v.x); h0.y = __float2bfloat16(v.y);
    h1.x = __float2bfloat16(v.z); h1.y = __float2bfloat16(v.w);
    l0.x = __float2bfloat16(v.x - __bfloat162float(h0.x));
    l0.y = __float2bfloat16(v.y - __bfloat162float(h0.y));
    l1.x = __float2bfloat16(v.z - __bfloat162float(h1.x));
    l1.y = __float2bfloat16(v.w - __bfloat162float(h1.y));
    ((__nv_bfloat162*)hi)[i*2]   = h0;
    ((__nv_bfloat162*)hi)[i*2+1] = h1;
    ((__nv_bfloat162*)lo)[i*2]   = l0;
    ((__nv_bfloat162*)lo)[i*2+1] = l1;
}

// ---------------------------------------------------------------------------
// HMMA GEMM: C[m,n] = sum_k A[m,k]*B[n,k], 3xBF16 split (AhBh + AhBl + AlBh),
// fp32 accum. Block 128x128, BK=32, 256 threads (8 warps, 4x2 grid, warp tile
// 32m x 64n), mma.sync m16n8k16, 2-stage cp.async pipeline.
// Smem tile rows padded to 40 bf16 (80B) -> conflict-free fragment LDS.
// OUTSEL 0/1: Q/K + fused RoPE -> g_Q/g_K [b,h,s,d] (bn == head, 128 cols == HD)
// OUTSEL 2: V; OUTSEL 3: ctx@Wo^T -> outp [m, n].
// ---------------------------------------------------------------------------
#define TILE_B 10240                 // 128 rows * 80B
#define STAGE_BYTES (4*TILE_B)       // Ah, Al, Bh, Bl
#define GSMEM_TOTAL (2*STAGE_BYTES)  // 81920; epilogue reuse needs 67584

__device__ __forceinline__ void stage_load(char* smc, int stage,
    const __nv_bfloat16* Ah, const __nv_bfloat16* Al,
    const __nv_bfloat16* Bh, const __nv_bfloat16* Bl,
    size_t arow, size_t brow, int k0, int tid)
{
    const __nv_bfloat16* srcs[4] = {Ah, Al, Bh, Bl};
#pragma unroll
    for (int t = 0; t < 4; t++) {
        const size_t rb = (t < 2) ? arow : brow;
        const __nv_bfloat16* s = srcs[t];
        char* base = smc + stage*STAGE_BYTES + t*TILE_B;
#pragma unroll
        for (int h = 0; h < 2; h++) {
            const int c = tid + h*256;          // 0..511
            const int row = c >> 2, col = c & 3;
            const uint32_t dst = smem_u32(base + row*80 + col*16);
            const void* gp = s + (rb + row)*(size_t)DD + k0 + col*8;
            asm volatile("cp.async.cg.shared.global [%0], [%1], 16;\n"
                         :: "r"(dst), "l"(gp) : "memory");
        }
    }
}

template<int OUTSEL>
__global__ __launch_bounds__(256, 2) void gemm_mma(float* __restrict__ outp,
                                                   const float* __restrict__ cosT,
                                                   const float* __restrict__ sinT)
{
    extern __shared__ char smc[];
    const int tid = threadIdx.x, wid = tid >> 5, lane = tid & 31;
    const int bn = blockIdx.x, bm = blockIdx.y;
    const int wm = wid >> 1, wn = wid & 1;
    const int g = lane >> 2, tg = lane & 3;

    const __nv_bfloat16* Ah = (OUTSEL == 3) ? g_Ch : g_Xh;
    const __nv_bfloat16* Al = (OUTSEL == 3) ? g_Cl : g_Xl;
    const __nv_bfloat16* Bh = (OUTSEL == 0) ? g_Wqh : (OUTSEL == 1) ? g_Wkh
                            : (OUTSEL == 2) ? g_Wvh : g_Woh;
    const __nv_bfloat16* Bl = (OUTSEL == 0) ? g_Wql : (OUTSEL == 1) ? g_Wkl
                            : (OUTSEL == 2) ? g_Wvl : g_Wol;

    const size_t arow = (size_t)bm * 128;
    const size_t brow = (size_t)bn * 128;

    float cacc[2][8][4];
#pragma unroll
    for (int mt = 0; mt < 2; mt++)
#pragma unroll
        for (int nt = 0; nt < 8; nt++)
#pragma unroll
            for (int q = 0; q < 4; q++) cacc[mt][nt][q] = 0.f;

    stage_load(smc, 0, Ah, Al, Bh, Bl, arow, brow, 0, tid);
    asm volatile("cp.async.commit_group;\n" ::: "memory");

    for (int ch = 0; ch < 64; ch++) {
        __syncthreads();   // prior iter's reads of the stage we're about to fill are done
        if (ch + 1 < 64) {
            stage_load(smc, (ch+1) & 1, Ah, Al, Bh, Bl, arow, brow, (ch+1)*32, tid);
            asm volatile("cp.async.commit_group;\n" ::: "memory");
            asm volatile("cp.async.wait_group 1;\n" ::: "memory");
        } else {
            asm volatile("cp.async.wait_group 0;\n" ::: "memory");
        }
        __syncthreads();

        const char* st = smc + (ch & 1)*STAGE_BYTES;
        const __nv_bfloat16* sAh = (const __nv_bfloat16*)(st);
        const __nv_bfloat16* sAl = (const __nv_bfloat16*)(st + TILE_B);
        const __nv_bfloat16* sBh = (const __nv_bfloat16*)(st + 2*TILE_B);
        const __nv_bfloat16* sBl = (const __nv_bfloat16*)(st + 3*TILE_B);

#pragma unroll
        for (int pass = 0; pass < 3; pass++) {
            const __nv_bfloat16* A_ = (pass == 2) ? sAl : sAh;
            const __nv_bfloat16* B_ = (pass == 1) ? sBl : sBh;
#pragma unroll
            for (int kk = 0; kk < 32; kk += 16) {
                uint32_t a[2][4], b[8][2];
#pragma unroll
                for (int mt = 0; mt < 2; mt++) {
                    const int r = wm*32 + mt*16 + g;
                    a[mt][0] = *(const uint32_t*)&A_[r*40     + kk + 2*tg];
                    a[mt][1] = *(const uint32_t*)&A_[(r+8)*40 + kk + 2*tg];
                    a[mt][2] = *(const uint32_t*)&A_[r*40     + kk + 2*tg + 8];
                    a[mt][3] = *(const uint32_t*)&A_[(r+8)*40 + kk + 2*tg + 8];
                }
#pragma unroll
                for (int nt = 0; nt < 8; nt++) {
                    const int r = wn*64 + nt*8 + g;
                    b[nt][0] = *(const uint32_t*)&B_[r*40 + kk + 2*tg];
                    b[nt][1] = *(const uint32_t*)&B_[r*40 + kk + 2*tg + 8];
                }
#pragma unroll
                for (int mt = 0; mt < 2; mt++)
#pragma unroll
                    for (int nt = 0; nt < 8; nt++)
                        mma16816(cacc[mt][nt], a[mt], b[nt]);
            }
        }
    }

    // ---- epilogue: regs -> smem bounce (for RoPE pairing) -> global ----
    __syncthreads();
    float* epi = (float*)smc;   // [128][132]
#pragma unroll
    for (int mt = 0; mt < 2; mt++)
#pragma unroll
        for (int nt = 0; nt < 8; nt++) {
            const int r0 = wm*32 + mt*16 + g;
            const int c0 = wn*64 + nt*8 + 2*tg;
            *(float2*)&epi[r0*132 + c0]     = make_float2(cacc[mt][nt][0], cacc[mt][nt][1]);
            *(float2*)&epi[(r0+8)*132 + c0] = make_float2(cacc[mt][nt][2], cacc[mt][nt][3]);
        }
    __syncthreads();

    for (int i = tid; i < 128*128; i += 256) {
        const int r = i >> 7, c = i & 127;
        const float v = epi[r*132 + c];
        const int m = bm*128 + r;
        if (OUTSEL <= 1) {
            const int b = m >> 11, s = m & 2047;
            const float cs = cosT[s*HDm + c];
            const float sn = sinT[s*HDm + c];
            const float o  = epi[r*132 + (c ^ 64)];
            const float res = (c < 64) ? (v*cs - o*sn) : (v*cs + o*sn);
            float* O = (OUTSEL == 0) ? g_Q : g_K;
            O[((size_t)(b*HH + bn)*SS + s)*HDm + c] = res;
        } else if (OUTSEL == 2) {
            const int b = m >> 11, s = m & 2047;
            g_V[((size_t)(b*HH + bn)*SS + s)*HDm + c] = v;
        } else {
            outp[(size_t)m*DD + bn*128 + c] = v;
        }
    }
}

// ---------------------------------------------------------------------------
// Flash attention (causal), fp32 (known-good), bf16 hi/lo ctx epilogue.
// ---------------------------------------------------------------------------
#define QT 32
#define KT 64
#define KSP 132
#define PSP 68
#define SM_KS 0
#define SM_VS (KT*KSP)
#define SM_QS (SM_VS + KT*HDm)
#define SM_PS (SM_QS + QT*HDm)
#define SM_TOT (SM_PS + QT*PSP)

__global__ __launch_bounds__(128) void flash_kernel()
{
    extern __shared__ float sm[];
    float* Ks = sm + SM_KS;
    float* Vs = sm + SM_VS;
    float* Qs = sm + SM_QS;
    float* Ps = sm + SM_PS;

    const int tid = threadIdx.x;
    const int qg = tid >> 4;
    const int kg = tid & 15;
    const int bh = blockIdx.y;
    const int q0 = blockIdx.x * QT;

    const float* Qg = g_Q + (size_t)bh * SS * HDm;
    const float* Kg = g_K + (size_t)bh * SS * HDm;
    const float* Vg = g_V + (size_t)bh * SS * HDm;

    for (int i = tid*4; i < QT*HDm; i += 128*4) {
        const int r = i >> 7, c = i & 127;
        *(float4*)&Qs[r*HDm + c] = *(const float4*)&Qg[(size_t)(q0 + r)*HDm + c];
    }

    float m[4], l[4], acc[4][8];
#pragma unroll
    for (int i = 0; i < 4; i++) {
        m[i] = -1e30f; l[i] = 0.f;
#pragma unroll
        for (int j = 0; j < 8; j++) acc[i][j] = 0.f;
    }

    const int ntiles = q0 / KT + 1;
    const float scale = 0.08838834764831845f;

    for (int t = 0; t < ntiles; t++) {
        const int j0 = t * KT;
        __syncthreads();
        for (int i = tid*4; i < KT*HDm; i += 128*4) {
            const int r = i >> 7, c = i & 127;
            *(float4*)&Ks[r*KSP + c] = *(const float4*)&Kg[(size_t)(j0 + r)*HDm + c];
            *(float4*)&Vs[r*HDm + c] = *(const float4*)&Vg[(size_t)(j0 + r)*HDm + c];
        }
        __syncthreads();

        float s4[4][4];
#pragma unroll
        for (int i = 0; i < 4; i++)
#pragma unroll
            for (int j = 0; j < 4; j++) s4[i][j] = 0.f;

#pragma unroll 4
        for (int d0 = 0; d0 < HDm; d0 += 4) {
            float4 qv[4], kv[4];
#pragma unroll
            for (int i = 0; i < 4; i++)
                qv[i] = *(const float4*)&Qs[(qg*4 + i)*HDm + d0];
#pragma unroll
            for (int j = 0; j < 4; j++)
                kv[j] = *(const float4*)&Ks[(kg*4 + j)*KSP + d0];
#pragma unroll
            for (int i = 0; i < 4; i++)
#pragma unroll
                for (int j = 0; j < 4; j++) {
                    s4[i][j] = fmaf(qv[i].x, kv[j].x, s4[i][j]);
                    s4[i][j] = fmaf(qv[i].y, kv[j].y, s4[i][j]);
                    s4[i][j] = fmaf(qv[i].z, kv[j].z, s4[i][j]);
                    s4[i][j] = fmaf(qv[i].w, kv[j].w, s4[i][j]);
                }
        }

        float corr[4];
#pragma unroll
        for (int i = 0; i < 4; i++) {
            const int qi = q0 + qg*4 + i;
            float tm = -1e30f;
#pragma unroll
            for (int j = 0; j < 4; j++) {
                const int kj = j0 + kg*4 + j;
                float v = (kj <= qi) ? s4[i][j]*scale : -1e30f;
                s4[i][j] = v;
                tm = fmaxf(tm, v);
            }
#pragma unroll
            for (int off = 8; off >= 1; off >>= 1)
                tm = fmaxf(tm, __shfl_xor_sync(0xffffffffu, tm, off));
            const float mn = fmaxf(m[i], tm);
            corr[i] = __expf(m[i] - mn);
            m[i] = mn;
            float rs = 0.f;
#pragma unroll
            for (int j = 0; j < 4; j++) {
                const float p = __expf(s4[i][j] - mn);
                s4[i][j] = p;
                rs += p;
            }
#pragma unroll
            for (int off = 8; off >= 1; off >>= 1)
                rs += __shfl_xor_sync(0xffffffffu, rs, off);
            l[i] = l[i]*corr[i] + rs;
        }

#pragma unroll
        for (int i = 0; i < 4; i++)
            *(float4*)&Ps[(qg*4 + i)*PSP + kg*4] =
                make_float4(s4[i][0], s4[i][1], s4[i][2], s4[i][3]);
#pragma unroll
        for (int i = 0; i < 4; i++)
#pragma unroll
            for (int d = 0; d < 8; d++) acc[i][d] *= corr[i];
        __syncthreads();

#pragma unroll 2
        for (int k = 0; k < KT; k++) {
            const float4 v0 = *(const float4*)&Vs[k*HDm + kg*8];
            const float4 v1 = *(const float4*)&Vs[k*HDm + kg*8 + 4];
#pragma unroll
            for (int i = 0; i < 4; i++) {
                const float p = Ps[(qg*4 + i)*PSP + k];
                acc[i][0] = fmaf(p, v0.x, acc[i][0]);
                acc[i][1] = fmaf(p, v0.y, acc[i][1]);
                acc[i][2] = fmaf(p, v0.z, acc[i][2]);
                acc[i][3] = fmaf(p, v0.w, acc[i][3]);
                acc[i][4] = fmaf(p, v1.x, acc[i][4]);
                acc[i][5] = fmaf(p, v1.y, acc[i][5]);
                acc[i][6] = fmaf(p, v1.z, acc[i][6]);
                acc[i][7] = fmaf(p, v1.w, acc[i][7]);
            }
        }
    }

    const int b = bh / HH, h = bh % HH;
#pragma unroll
    for (int i = 0; i < 4; i++) {
        const float inv = 1.f / l[i];
        const int qrow = q0 + qg*4 + i;
        const size_t base = ((size_t)(b*SS + qrow))*DD + h*HDm + kg*8;
#pragma unroll
        for (int j = 0; j < 8; j++) {
            const float v = acc[i][j] * inv;
            const __nv_bfloat16 hh = __float2bfloat16(v);
            g_Ch[base + j] = hh;
            g_Cl[base + j] = __float2bfloat16(v - __bfloat162float(hh));
        }
    }
}

// ---------------------------------------------------------------------------
extern "C" void kernel_launch(void* const* d_in, const int* in_sizes, int n_in,
                              void* d_out, int out_size)
{
    const float* x    = (const float*)d_in[0];
    const float* Wq   = (const float*)d_in[1];
    const float* Wk   = (const float*)d_in[2];
    const float* Wv   = (const float*)d_in[3];
    const float* Wo   = (const float*)d_in[4];
    const float* cosT = (const float*)d_in[5];
    const float* sinT = (const float*)d_in[6];
    float* out = (float*)d_out;

    cudaFuncSetAttribute(gemm_mma<0>, cudaFuncAttributeMaxDynamicSharedMemorySize, GSMEM_TOTAL);
    cudaFuncSetAttribute(gemm_mma<1>, cudaFuncAttributeMaxDynamicSharedMemorySize, GSMEM_TOTAL);
    cudaFuncSetAttribute(gemm_mma<2>, cudaFuncAttributeMaxDynamicSharedMemorySize, GSMEM_TOTAL);
    cudaFuncSetAttribute(gemm_mma<3>, cudaFuncAttributeMaxDynamicSharedMemorySize, GSMEM_TOTAL);
    cudaFuncSetAttribute(flash_kernel, cudaFuncAttributeMaxDynamicSharedMemorySize,
                         SM_TOT * (int)sizeof(float));

    const int nx4 = MM * DD / 4;
    const int nw4 = DD * DD / 4;
    split_kernel<0><<<nx4 / 256, 256>>>(x,  nx4);
    split_kernel<1><<<nw4 / 256, 256>>>(Wq, nw4);
    split_kernel<2><<<nw4 / 256, 256>>>(Wk, nw4);
    split_kernel<3><<<nw4 / 256, 256>>>(Wv, nw4);
    split_kernel<4><<<nw4 / 256, 256>>>(Wo, nw4);

    dim3 gg(DD / 128, MM / 128);   // (16, 32)
    gemm_mma<0><<<gg, 256, GSMEM_TOTAL>>>(nullptr, cosT, sinT);
    gemm_mma<1><<<gg, 256, GSMEM_TOTAL>>>(nullptr, cosT, sinT);
    gemm_mma<2><<<gg, 256, GSMEM_TOTAL>>>(nullptr, cosT, sinT);

    flash_kernel<<<dim3(SS/QT, Bb*HH), 128, SM_TOT * sizeof(float)>>>();

    gemm_mma<3><<<gg, 256, GSMEM_TOTAL>>>(out, cosT, sinT);
}

// round 9
// speedup vs baseline: 2.8888x; 1.8784x over previous
#include <cuda_runtime.h>
#include <cuda_bf16.h>
#include <math.h>
#include <stdint.h>

#define Bb 2
#define SS 2048
#define DD 2048
#define HH 16
#define HDm 128
#define MM (Bb*SS)   // 4096

// ---------------------------------------------------------------------------
// Device-global scratch (no allocations allowed)
// ---------------------------------------------------------------------------
__device__ __align__(16) __nv_bfloat16 g_Xh[(size_t)MM*DD],  g_Xl[(size_t)MM*DD];
__device__ __align__(16) __nv_bfloat16 g_Wqh[(size_t)DD*DD], g_Wql[(size_t)DD*DD];
__device__ __align__(16) __nv_bfloat16 g_Wkh[(size_t)DD*DD], g_Wkl[(size_t)DD*DD];
__device__ __align__(16) __nv_bfloat16 g_Wvh[(size_t)DD*DD], g_Wvl[(size_t)DD*DD];
__device__ __align__(16) __nv_bfloat16 g_Woh[(size_t)DD*DD], g_Wol[(size_t)DD*DD];
__device__ __align__(16) __nv_bfloat16 g_Ch[(size_t)MM*DD],  g_Cl[(size_t)MM*DD];

// post-RoPE Q/K in bf16 hi/lo, [b,h,s,d]
__device__ __align__(16) __nv_bfloat16 g_Qh[(size_t)MM*DD], g_Ql[(size_t)MM*DD];
__device__ __align__(16) __nv_bfloat16 g_Kh[(size_t)MM*DD], g_Kl[(size_t)MM*DD];
// V transposed, [b,h,d,s], bf16 hi/lo
__device__ __align__(16) __nv_bfloat16 g_VhT[(size_t)MM*DD], g_VlT[(size_t)MM*DD];

// ---------------------------------------------------------------------------
// helpers (arch-portable PTX only)
// ---------------------------------------------------------------------------
__device__ __forceinline__ uint32_t smem_u32(const void* p) {
    uint32_t a;
    asm("{ .reg .u64 t; cvta.to.shared.u64 t, %1; cvt.u32.u64 %0, t; }"
        : "=r"(a) : "l"(p));
    return a;
}

__device__ __forceinline__ void mma16816(float* c, const uint32_t* a, const uint32_t* b) {
    asm volatile(
        "mma.sync.aligned.m16n8k16.row.col.f32.bf16.bf16.f32 "
        "{%0,%1,%2,%3}, {%4,%5,%6,%7}, {%8,%9}, {%0,%1,%2,%3};"
        : "+f"(c[0]), "+f"(c[1]), "+f"(c[2]), "+f"(c[3])
        : "r"(a[0]), "r"(a[1]), "r"(a[2]), "r"(a[3]), "r"(b[0]), "r"(b[1]));
}

__device__ __forceinline__ void cpasync16(uint32_t dst, const void* src) {
    asm volatile("cp.async.cg.shared.global [%0], [%1], 16;\n" :: "r"(dst), "l"(src) : "memory");
}

__device__ __forceinline__ uint32_t pack_bf2(float a, float b) {
    __nv_bfloat162 t;
    t.x = __float2bfloat16(a);
    t.y = __float2bfloat16(b);
    return *(uint32_t*)&t;
}

// ---------------------------------------------------------------------------
// fp32 -> bf16 hi/lo splitter
// ---------------------------------------------------------------------------
template<int SEL>
__global__ __launch_bounds__(256) void split_kernel(const float* __restrict__ src, int n4)
{
    const int i = blockIdx.x * 256 + threadIdx.x;
    if (i >= n4) return;
    __nv_bfloat16* hi = (SEL==0) ? g_Xh : (SEL==1) ? g_Wqh : (SEL==2) ? g_Wkh
                      : (SEL==3) ? g_Wvh : g_Woh;
    __nv_bfloat16* lo = (SEL==0) ? g_Xl : (SEL==1) ? g_Wql : (SEL==2) ? g_Wkl
                      : (SEL==3) ? g_Wvl : g_Wol;
    const float4 v = ((const float4*)src)[i];
    __nv_bfloat162 h0, h1, l0, l1;
    h0.x = __float2bfloat16(v.x); h0.y = __float2bfloat16(v.y);
    h1.x = __float2bfloat16(v.z); h1.y = __float2bfloat16(v.w);
    l0.x = __float2bfloat16(v.x - __bfloat162float(h0.x));
    l0.y = __float2bfloat16(v.y - __bfloat162float(h0.y));
    l1.x = __float2bfloat16(v.z - __bfloat162float(h1.x));
    l1.y = __float2bfloat16(v.w - __bfloat162float(h1.y));
    ((__nv_bfloat162*)hi)[i*2]   = h0;
    ((__nv_bfloat162*)hi)[i*2+1] = h1;
    ((__nv_bfloat162*)lo)[i*2]   = l0;
    ((__nv_bfloat162*)lo)[i*2+1] = l1;
}

// ---------------------------------------------------------------------------
// HMMA GEMM. Epilogues:
// OUTSEL 0/1: Q/K + fused RoPE -> bf16 hi/lo [b,h,s,d]
// OUTSEL 2:   V -> TRANSPOSED bf16 hi/lo [b,h,d,s]
// OUTSEL 3:   ctx@Wo^T -> fp32 outp
// ---------------------------------------------------------------------------
#define TILE_B 10240
#define STAGE_BYTES (4*TILE_B)
#define GSMEM_TOTAL (2*STAGE_BYTES)

__device__ __forceinline__ void stage_load(char* smc, int stage,
    const __nv_bfloat16* Ah, const __nv_bfloat16* Al,
    const __nv_bfloat16* Bh, const __nv_bfloat16* Bl,
    size_t arow, size_t brow, int k0, int tid)
{
    const __nv_bfloat16* srcs[4] = {Ah, Al, Bh, Bl};
#pragma unroll
    for (int t = 0; t < 4; t++) {
        const size_t rb = (t < 2) ? arow : brow;
        const __nv_bfloat16* s = srcs[t];
        char* base = smc + stage*STAGE_BYTES + t*TILE_B;
#pragma unroll
        for (int h = 0; h < 2; h++) {
            const int c = tid + h*256;
            const int row = c >> 2, col = c & 3;
            cpasync16(smem_u32(base + row*80 + col*16), s + (rb + row)*(size_t)DD + k0 + col*8);
        }
    }
}

template<int OUTSEL>
__global__ __launch_bounds__(256, 2) void gemm_mma(float* __restrict__ outp,
                                                   const float* __restrict__ cosT,
                                                   const float* __restrict__ sinT)
{
    extern __shared__ char smc[];
    const int tid = threadIdx.x, wid = tid >> 5, lane = tid & 31;
    const int bn = blockIdx.x, bm = blockIdx.y;
    const int wm = wid >> 1, wn = wid & 1;
    const int g = lane >> 2, tg = lane & 3;

    const __nv_bfloat16* Ah = (OUTSEL == 3) ? g_Ch : g_Xh;
    const __nv_bfloat16* Al = (OUTSEL == 3) ? g_Cl : g_Xl;
    const __nv_bfloat16* Bh = (OUTSEL == 0) ? g_Wqh : (OUTSEL == 1) ? g_Wkh
                            : (OUTSEL == 2) ? g_Wvh : g_Woh;
    const __nv_bfloat16* Bl = (OUTSEL == 0) ? g_Wql : (OUTSEL == 1) ? g_Wkl
                            : (OUTSEL == 2) ? g_Wvl : g_Wol;

    const size_t arow = (size_t)bm * 128;
    const size_t brow = (size_t)bn * 128;

    float cacc[2][8][4];
#pragma unroll
    for (int mt = 0; mt < 2; mt++)
#pragma unroll
        for (int nt = 0; nt < 8; nt++)
#pragma unroll
            for (int q = 0; q < 4; q++) cacc[mt][nt][q] = 0.f;

    stage_load(smc, 0, Ah, Al, Bh, Bl, arow, brow, 0, tid);
    asm volatile("cp.async.commit_group;\n" ::: "memory");

    for (int ch = 0; ch < 64; ch++) {
        __syncthreads();
        if (ch + 1 < 64) {
            stage_load(smc, (ch+1) & 1, Ah, Al, Bh, Bl, arow, brow, (ch+1)*32, tid);
            asm volatile("cp.async.commit_group;\n" ::: "memory");
            asm volatile("cp.async.wait_group 1;\n" ::: "memory");
        } else {
            asm volatile("cp.async.wait_group 0;\n" ::: "memory");
        }
        __syncthreads();

        const char* st = smc + (ch & 1)*STAGE_BYTES;
        const __nv_bfloat16* sAh = (const __nv_bfloat16*)(st);
        const __nv_bfloat16* sAl = (const __nv_bfloat16*)(st + TILE_B);
        const __nv_bfloat16* sBh = (const __nv_bfloat16*)(st + 2*TILE_B);
        const __nv_bfloat16* sBl = (const __nv_bfloat16*)(st + 3*TILE_B);

#pragma unroll
        for (int pass = 0; pass < 3; pass++) {
            const __nv_bfloat16* A_ = (pass == 2) ? sAl : sAh;
            const __nv_bfloat16* B_ = (pass == 1) ? sBl : sBh;
#pragma unroll
            for (int kk = 0; kk < 32; kk += 16) {
                uint32_t a[2][4], b[8][2];
#pragma unroll
                for (int mt = 0; mt < 2; mt++) {
                    const int r = wm*32 + mt*16 + g;
                    a[mt][0] = *(const uint32_t*)&A_[r*40     + kk + 2*tg];
                    a[mt][1] = *(const uint32_t*)&A_[(r+8)*40 + kk + 2*tg];
                    a[mt][2] = *(const uint32_t*)&A_[r*40     + kk + 2*tg + 8];
                    a[mt][3] = *(const uint32_t*)&A_[(r+8)*40 + kk + 2*tg + 8];
                }
#pragma unroll
                for (int nt = 0; nt < 8; nt++) {
                    const int r = wn*64 + nt*8 + g;
                    b[nt][0] = *(const uint32_t*)&B_[r*40 + kk + 2*tg];
                    b[nt][1] = *(const uint32_t*)&B_[r*40 + kk + 2*tg + 8];
                }
#pragma unroll
                for (int mt = 0; mt < 2; mt++)
#pragma unroll
                    for (int nt = 0; nt < 8; nt++)
                        mma16816(cacc[mt][nt], a[mt], b[nt]);
            }
        }
    }

    __syncthreads();
    float* epi = (float*)smc;   // [128][132]
#pragma unroll
    for (int mt = 0; mt < 2; mt++)
#pragma unroll
        for (int nt = 0; nt < 8; nt++) {
            const int r0 = wm*32 + mt*16 + g;
            const int c0 = wn*64 + nt*8 + 2*tg;
            *(float2*)&epi[r0*132 + c0]     = make_float2(cacc[mt][nt][0], cacc[mt][nt][1]);
            *(float2*)&epi[(r0+8)*132 + c0] = make_float2(cacc[mt][nt][2], cacc[mt][nt][3]);
        }
    __syncthreads();

    if (OUTSEL <= 1) {
        __nv_bfloat16* Oh = (OUTSEL == 0) ? g_Qh : g_Kh;
        __nv_bfloat16* Ol = (OUTSEL == 0) ? g_Ql : g_Kl;
        for (int i = tid; i < 128*128; i += 256) {
            const int r = i >> 7, c = i & 127;
            const float v = epi[r*132 + c];
            const int m = bm*128 + r;
            const int b = m >> 11, s = m & 2047;
            const float cs = cosT[s*HDm + c];
            const float sn = sinT[s*HDm + c];
            const float o  = epi[r*132 + (c ^ 64)];
            const float res = (c < 64) ? (v*cs - o*sn) : (v*cs + o*sn);
            const size_t idx = ((size_t)(b*HH + bn)*SS + s)*HDm + c;
            const __nv_bfloat16 hh = __float2bfloat16(res);
            Oh[idx] = hh;
            Ol[idx] = __float2bfloat16(res - __bfloat162float(hh));
        }
    } else if (OUTSEL == 2) {
        // transposed V: [b,h,d,s]
        const int b = (bm*128) >> 11;
        const int s0 = (bm*128) & 2047;
        for (int i = tid; i < 128*16; i += 256) {
            const int c  = i & 127;     // d
            const int rg = i >> 7;      // row group (8 rows)
            const int r0 = rg*8;
            __nv_bfloat16 hbuf[8], lbuf[8];
#pragma unroll
            for (int j = 0; j < 8; j++) {
                const float v = epi[(r0+j)*132 + c];
                hbuf[j] = __float2bfloat16(v);
                lbuf[j] = __float2bfloat16(v - __bfloat162float(hbuf[j]));
            }
            const size_t dst = ((size_t)(b*HH + bn)*HDm + c)*SS + s0 + r0;
            *(uint4*)&g_VhT[dst] = *(uint4*)hbuf;
            *(uint4*)&g_VlT[dst] = *(uint4*)lbuf;
        }
    } else {
        for (int i = tid; i < 128*128; i += 256) {
            const int r = i >> 7, c = i & 127;
            outp[(size_t)(bm*128 + r)*DD + bn*128 + c] = epi[r*132 + c];
        }
    }
}

// ---------------------------------------------------------------------------
// Flash attention on mma.sync bf16 with 3x hi/lo splits.
// Block: 64 q rows, 128 threads (4 warps, warp = 16 q rows). K/V tiles 64,
// DOUBLE-BUFFERED (cp.async pipeline). Heavy-first block scheduling.
// smem rows: Q/K padded to 136 bf16 (272B); V^T padded to 72 bf16 (144B).
// ---------------------------------------------------------------------------
#define QROWB 272
#define VROWB 144
#define OFF_QH 0
#define OFF_QL (64*QROWB)                  // 17408
#define STG0   (2*64*QROWB)                // 34816: start of stage buffers
#define SOFF_KH 0
#define SOFF_KL (64*QROWB)                 // 17408
#define SOFF_VH (2*64*QROWB)               // 34816
#define SOFF_VL (2*64*QROWB + 128*VROWB)   // 53248
#define STG_SZ  (2*64*QROWB + 2*128*VROWB) // 71680
#define FSMEM   (STG0 + 2*STG_SZ)          // 178176

__device__ __forceinline__ void load_kv(uint32_t sb, int stage,
                                        size_t qkb, size_t vb, int j0, int tid)
{
    const uint32_t base = sb + STG0 + stage*STG_SZ;
#pragma unroll
    for (int j = 0; j < 8; j++) {
        const int idx = j*128 + tid;
        const int row = idx >> 4, c16 = idx & 15;
        cpasync16(base + SOFF_KH + row*QROWB + c16*16, g_Kh + qkb + (size_t)(j0+row)*HDm + c16*8);
        cpasync16(base + SOFF_KL + row*QROWB + c16*16, g_Kl + qkb + (size_t)(j0+row)*HDm + c16*8);
        const int vrow = idx >> 3, c8 = idx & 7;
        cpasync16(base + SOFF_VH + vrow*VROWB + c8*16, g_VhT + vb + (size_t)vrow*SS + j0 + c8*8);
        cpasync16(base + SOFF_VL + vrow*VROWB + c8*16, g_VlT + vb + (size_t)vrow*SS + j0 + c8*8);
    }
}

__global__ __launch_bounds__(128) void flash_mma()
{
    extern __shared__ char fs[];
    const uint32_t sb = smem_u32(fs);
    const int tid = threadIdx.x, wid = tid >> 5, lane = tid & 31;
    const int g = lane >> 4 ? 0 : 0;   // placeholder to keep regs tight (unused)
    const int gg = lane >> 2, tg = lane & 3;
    const int bh = blockIdx.y;
    const int q0 = (gridDim.x - 1 - blockIdx.x) * 64;   // heavy-first (LPT)
    const int wq = wid * 16;

    const size_t qkb = (size_t)bh * SS * HDm;   // [bh][s][d]
    const size_t vb  = (size_t)bh * HDm * SS;   // [bh][d][s]

    // load Q hi/lo (once)
#pragma unroll
    for (int j = 0; j < 8; j++) {
        const int idx = j*128 + tid;
        const int row = idx >> 4, c16 = idx & 15;
        cpasync16(sb + OFF_QH + row*QROWB + c16*16, g_Qh + qkb + (size_t)(q0+row)*HDm + c16*8);
        cpasync16(sb + OFF_QL + row*QROWB + c16*16, g_Ql + qkb + (size_t)(q0+row)*HDm + c16*8);
    }
    asm volatile("cp.async.commit_group;\n" ::: "memory");

    const int ntiles = q0/64 + 1;
    load_kv(sb, 0, qkb, vb, 0, tid);
    asm volatile("cp.async.commit_group;\n" ::: "memory");

    float m2[2] = {-1e30f, -1e30f}, l2[2] = {0.f, 0.f};
    float oacc[16][4];
#pragma unroll
    for (int i = 0; i < 16; i++)
#pragma unroll
        for (int q = 0; q < 4; q++) oacc[i][q] = 0.f;

    const float scale = 0.08838834764831845f;
    const __nv_bfloat16* sQh = (const __nv_bfloat16*)(fs + OFF_QH);
    const __nv_bfloat16* sQl = (const __nv_bfloat16*)(fs + OFF_QL);

    for (int t = 0; t < ntiles; t++) {
        const int j0 = t * 64;
        if (t + 1 < ntiles) {
            load_kv(sb, (t+1) & 1, qkb, vb, (t+1)*64, tid);
            asm volatile("cp.async.commit_group;\n" ::: "memory");
            asm volatile("cp.async.wait_group 1;\n" ::: "memory");
        } else {
            asm volatile("cp.async.wait_group 0;\n" ::: "memory");
        }
        __syncthreads();

        const char* stg = fs + STG0 + (t & 1)*STG_SZ;
        const __nv_bfloat16* sKh = (const __nv_bfloat16*)(stg + SOFF_KH);
        const __nv_bfloat16* sKl = (const __nv_bfloat16*)(stg + SOFF_KL);
        const __nv_bfloat16* sVh = (const __nv_bfloat16*)(stg + SOFF_VH);
        const __nv_bfloat16* sVl = (const __nv_bfloat16*)(stg + SOFF_VL);

        // ---- scores: S = Q K^T via 3 passes ----
        float sacc[8][4];
#pragma unroll
        for (int nt = 0; nt < 8; nt++)
#pragma unroll
            for (int q = 0; q < 4; q++) sacc[nt][q] = 0.f;

#pragma unroll
        for (int pass = 0; pass < 3; pass++) {
            const __nv_bfloat16* A_ = (pass == 2) ? sQl : sQh;
            const __nv_bfloat16* B_ = (pass == 1) ? sKl : sKh;
#pragma unroll
            for (int kk = 0; kk < 128; kk += 16) {
                uint32_t a[4];
                const int r = wq + gg;
                a[0] = *(const uint32_t*)&A_[r*136     + kk + 2*tg];
                a[1] = *(const uint32_t*)&A_[(r+8)*136 + kk + 2*tg];
                a[2] = *(const uint32_t*)&A_[r*136     + kk + 2*tg + 8];
                a[3] = *(const uint32_t*)&A_[(r+8)*136 + kk + 2*tg + 8];
#pragma unroll
                for (int nt = 0; nt < 8; nt++) {
                    uint32_t b[2];
                    const int kr = nt*8 + gg;
                    b[0] = *(const uint32_t*)&B_[kr*136 + kk + 2*tg];
                    b[1] = *(const uint32_t*)&B_[kr*136 + kk + 2*tg + 8];
                    mma16816(sacc[nt], a, b);
                }
            }
        }

        // ---- mask + online softmax (rows gg and gg+8) ----
        float corr[2];
#pragma unroll
        for (int h2 = 0; h2 < 2; h2++) {
            const int r = q0 + wq + gg + h2*8;
            float mx = -1e30f;
#pragma unroll
            for (int nt = 0; nt < 8; nt++)
#pragma unroll
                for (int e = 0; e < 2; e++) {
                    const int col = j0 + nt*8 + 2*tg + e;
                    float v = (col <= r) ? sacc[nt][h2*2+e]*scale : -1e30f;
                    sacc[nt][h2*2+e] = v;
                    mx = fmaxf(mx, v);
                }
            mx = fmaxf(mx, __shfl_xor_sync(0xffffffffu, mx, 1));
            mx = fmaxf(mx, __shfl_xor_sync(0xffffffffu, mx, 2));
            const float mn = fmaxf(m2[h2], mx);
            corr[h2] = __expf(m2[h2] - mn);
            m2[h2] = mn;
            float rs = 0.f;
#pragma unroll
            for (int nt = 0; nt < 8; nt++)
#pragma unroll
                for (int e = 0; e < 2; e++) {
                    const float p = __expf(sacc[nt][h2*2+e] - mn);
                    sacc[nt][h2*2+e] = p;
                    rs += p;
                }
            rs += __shfl_xor_sync(0xffffffffu, rs, 1);
            rs += __shfl_xor_sync(0xffffffffu, rs, 2);
            l2[h2] = l2[h2]*corr[h2] + rs;
        }
#pragma unroll
        for (int nt2 = 0; nt2 < 16; nt2++) {
            oacc[nt2][0] *= corr[0]; oacc[nt2][1] *= corr[0];
            oacc[nt2][2] *= corr[1]; oacc[nt2][3] *= corr[1];
        }

        // ---- pack P hi/lo into A fragments (register-only) ----
        uint32_t aPh[4][4], aPl[4][4];
#pragma unroll
        for (int jp = 0; jp < 4; jp++) {
#pragma unroll
            for (int f = 0; f < 4; f++) {
                const int nt = 2*jp + (f >> 1);
                const int e0 = (f & 1)*2;
                const float p0 = sacc[nt][e0], p1 = sacc[nt][e0+1];
                const __nv_bfloat16 h0 = __float2bfloat16(p0);
                const __nv_bfloat16 h1 = __float2bfloat16(p1);
                __nv_bfloat162 hp; hp.x = h0; hp.y = h1;
                aPh[jp][f] = *(uint32_t*)&hp;
                aPl[jp][f] = pack_bf2(p0 - __bfloat162float(h0), p1 - __bfloat162float(h1));
            }
        }

        // ---- PV: oacc += Ph Vh + Ph Vl + Pl Vh ----
#pragma unroll
        for (int jp = 0; jp < 4; jp++) {
#pragma unroll
            for (int nt2 = 0; nt2 < 16; nt2++) {
                const int dr = nt2*8 + gg;
                uint32_t bhf[2], blf[2];
                bhf[0] = *(const uint32_t*)&sVh[dr*72 + jp*16 + 2*tg];
                bhf[1] = *(const uint32_t*)&sVh[dr*72 + jp*16 + 2*tg + 8];
                blf[0] = *(const uint32_t*)&sVl[dr*72 + jp*16 + 2*tg];
                blf[1] = *(const uint32_t*)&sVl[dr*72 + jp*16 + 2*tg + 8];
                mma16816(oacc[nt2], aPh[jp], bhf);
                mma16816(oacc[nt2], aPh[jp], blf);
                mma16816(oacc[nt2], aPl[jp], bhf);
            }
        }
        __syncthreads();   // compute done before next iter overwrites stage (t+1)&1
    }

    // ---- epilogue: ctx bf16 hi/lo, [b, s, h*HD + d] ----
    const int b = bh / HH, h = bh % HH;
#pragma unroll
    for (int h2 = 0; h2 < 2; h2++) {
        const float inv = 1.f / l2[h2];
        const int r = q0 + wq + gg + h2*8;
        const size_t base = ((size_t)(b*SS + r))*DD + h*HDm;
#pragma unroll
        for (int nt2 = 0; nt2 < 16; nt2++) {
            const int d = nt2*8 + 2*tg;
            const float v0 = oacc[nt2][h2*2]   * inv;
            const float v1 = oacc[nt2][h2*2+1] * inv;
            const __nv_bfloat16 h0 = __float2bfloat16(v0);
            const __nv_bfloat16 h1 = __float2bfloat16(v1);
            __nv_bfloat162 hp; hp.x = h0; hp.y = h1;
            *(uint32_t*)&g_Ch[base + d] = *(uint32_t*)&hp;
            *(uint32_t*)&g_Cl[base + d] =
                pack_bf2(v0 - __bfloat162float(h0), v1 - __bfloat162float(h1));
        }
    }
}

// ---------------------------------------------------------------------------
extern "C" void kernel_launch(void* const* d_in, const int* in_sizes, int n_in,
                              void* d_out, int out_size)
{
    const float* x    = (const float*)d_in[0];
    const float* Wq   = (const float*)d_in[1];
    const float* Wk   = (const float*)d_in[2];
    const float* Wv   = (const float*)d_in[3];
    const float* Wo   = (const float*)d_in[4];
    const float* cosT = (const float*)d_in[5];
    const float* sinT = (const float*)d_in[6];
    float* out = (float*)d_out;

    cudaFuncSetAttribute(gemm_mma<0>, cudaFuncAttributeMaxDynamicSharedMemorySize, GSMEM_TOTAL);
    cudaFuncSetAttribute(gemm_mma<1>, cudaFuncAttributeMaxDynamicSharedMemorySize, GSMEM_TOTAL);
    cudaFuncSetAttribute(gemm_mma<2>, cudaFuncAttributeMaxDynamicSharedMemorySize, GSMEM_TOTAL);
    cudaFuncSetAttribute(gemm_mma<3>, cudaFuncAttributeMaxDynamicSharedMemorySize, GSMEM_TOTAL);
    cudaFuncSetAttribute(flash_mma, cudaFuncAttributeMaxDynamicSharedMemorySize, FSMEM);

    const int nx4 = MM * DD / 4;
    const int nw4 = DD * DD / 4;
    split_kernel<0><<<nx4 / 256, 256>>>(x,  nx4);
    split_kernel<1><<<nw4 / 256, 256>>>(Wq, nw4);
    split_kernel<2><<<nw4 / 256, 256>>>(Wk, nw4);
    split_kernel<3><<<nw4 / 256, 256>>>(Wv, nw4);
    split_kernel<4><<<nw4 / 256, 256>>>(Wo, nw4);

    dim3 gg(DD / 128, MM / 128);   // (16, 32)
    gemm_mma<0><<<gg, 256, GSMEM_TOTAL>>>(nullptr, cosT, sinT);
    gemm_mma<1><<<gg, 256, GSMEM_TOTAL>>>(nullptr, cosT, sinT);
    gemm_mma<2><<<gg, 256, GSMEM_TOTAL>>>(nullptr, cosT, sinT);

    flash_mma<<<dim3(SS/64, Bb*HH), 128, FSMEM>>>();

    gemm_mma<3><<<gg, 256, GSMEM_TOTAL>>>(out, cosT, sinT);
}

// round 10
// speedup vs baseline: 3.0418x; 1.0529x over previous
#include <cuda_runtime.h>
#include <cuda_bf16.h>
#include <math.h>
#include <stdint.h>

#define Bb 2
#define SS 2048
#define DD 2048
#define HH 16
#define HDm 128
#define MM (Bb*SS)   // 4096

// ---------------------------------------------------------------------------
// Device-global scratch (no allocations allowed)
// ---------------------------------------------------------------------------
__device__ __align__(16) __nv_bfloat16 g_Xh[(size_t)MM*DD],  g_Xl[(size_t)MM*DD];
__device__ __align__(16) __nv_bfloat16 g_Wqh[(size_t)DD*DD], g_Wql[(size_t)DD*DD];
__device__ __align__(16) __nv_bfloat16 g_Wkh[(size_t)DD*DD], g_Wkl[(size_t)DD*DD];
__device__ __align__(16) __nv_bfloat16 g_Wvh[(size_t)DD*DD], g_Wvl[(size_t)DD*DD];
__device__ __align__(16) __nv_bfloat16 g_Woh[(size_t)DD*DD], g_Wol[(size_t)DD*DD];
__device__ __align__(16) __nv_bfloat16 g_Ch[(size_t)MM*DD],  g_Cl[(size_t)MM*DD];

// post-RoPE Q/K in bf16 hi/lo, [b,h,s,d]
__device__ __align__(16) __nv_bfloat16 g_Qh[(size_t)MM*DD], g_Ql[(size_t)MM*DD];
__device__ __align__(16) __nv_bfloat16 g_Kh[(size_t)MM*DD], g_Kl[(size_t)MM*DD];
// V transposed, [b,h,d,s], bf16 hi/lo
__device__ __align__(16) __nv_bfloat16 g_VhT[(size_t)MM*DD], g_VlT[(size_t)MM*DD];

// ---------------------------------------------------------------------------
// helpers (arch-portable PTX only)
// ---------------------------------------------------------------------------
__device__ __forceinline__ uint32_t smem_u32(const void* p) {
    uint32_t a;
    asm("{ .reg .u64 t; cvta.to.shared.u64 t, %1; cvt.u32.u64 %0, t; }"
        : "=r"(a) : "l"(p));
    return a;
}

__device__ __forceinline__ void mma16816(float* c, const uint32_t* a, const uint32_t* b) {
    asm volatile(
        "mma.sync.aligned.m16n8k16.row.col.f32.bf16.bf16.f32 "
        "{%0,%1,%2,%3}, {%4,%5,%6,%7}, {%8,%9}, {%0,%1,%2,%3};"
        : "+f"(c[0]), "+f"(c[1]), "+f"(c[2]), "+f"(c[3])
        : "r"(a[0]), "r"(a[1]), "r"(a[2]), "r"(a[3]), "r"(b[0]), "r"(b[1]));
}

__device__ __forceinline__ void cpasync16(uint32_t dst, const void* src) {
    asm volatile("cp.async.cg.shared.global [%0], [%1], 16;\n" :: "r"(dst), "l"(src) : "memory");
}

__device__ __forceinline__ uint32_t pack_bf2(float a, float b) {
    __nv_bfloat162 t;
    t.x = __float2bfloat16(a);
    t.y = __float2bfloat16(b);
    return *(uint32_t*)&t;
}

// ---------------------------------------------------------------------------
// fp32 -> bf16 hi/lo splitter
// ---------------------------------------------------------------------------
template<int SEL>
__global__ __launch_bounds__(256) void split_kernel(const float* __restrict__ src, int n4)
{
    const int i = blockIdx.x * 256 + threadIdx.x;
    if (i >= n4) return;
    __nv_bfloat16* hi = (SEL==0) ? g_Xh : (SEL==1) ? g_Wqh : (SEL==2) ? g_Wkh
                      : (SEL==3) ? g_Wvh : g_Woh;
    __nv_bfloat16* lo = (SEL==0) ? g_Xl : (SEL==1) ? g_Wql : (SEL==2) ? g_Wkl
                      : (SEL==3) ? g_Wvl : g_Wol;
    const float4 v = ((const float4*)src)[i];
    __nv_bfloat162 h0, h1, l0, l1;
    h0.x = __float2bfloat16(v.x); h0.y = __float2bfloat16(v.y);
    h1.x = __float2bfloat16(v.z); h1.y = __float2bfloat16(v.w);
    l0.x = __float2bfloat16(v.x - __bfloat162float(h0.x));
    l0.y = __float2bfloat16(v.y - __bfloat162float(h0.y));
    l1.x = __float2bfloat16(v.z - __bfloat162float(h1.x));
    l1.y = __float2bfloat16(v.w - __bfloat162float(h1.y));
    ((__nv_bfloat162*)hi)[i*2]   = h0;
    ((__nv_bfloat162*)hi)[i*2+1] = h1;
    ((__nv_bfloat162*)lo)[i*2]   = l0;
    ((__nv_bfloat162*)lo)[i*2+1] = l1;
}

// ---------------------------------------------------------------------------
// HMMA GEMM mainloop (shared). 128x128 tile, BK=32, 256 threads, 2-stage.
// ---------------------------------------------------------------------------
#define TILE_B 10240
#define STAGE_BYTES (4*TILE_B)
#define GSMEM_TOTAL (2*STAGE_BYTES)

__device__ __forceinline__ void stage_load(char* smc, int stage,
    const __nv_bfloat16* Ah, const __nv_bfloat16* Al,
    const __nv_bfloat16* Bh, const __nv_bfloat16* Bl,
    size_t arow, size_t brow, int k0, int tid)
{
    const __nv_bfloat16* srcs[4] = {Ah, Al, Bh, Bl};
#pragma unroll
    for (int t = 0; t < 4; t++) {
        const size_t rb = (t < 2) ? arow : brow;
        const __nv_bfloat16* s = srcs[t];
        char* base = smc + stage*STAGE_BYTES + t*TILE_B;
#pragma unroll
        for (int h = 0; h < 2; h++) {
            const int c = tid + h*256;
            const int row = c >> 2, col = c & 3;
            cpasync16(smem_u32(base + row*80 + col*16), s + (rb + row)*(size_t)DD + k0 + col*8);
        }
    }
}

__device__ __forceinline__ void gemm_mainloop(char* smc,
    const __nv_bfloat16* Ah, const __nv_bfloat16* Al,
    const __nv_bfloat16* Bh, const __nv_bfloat16* Bl,
    size_t arow, size_t brow, int tid, float cacc[2][8][4])
{
    const int wid = tid >> 5, lane = tid & 31;
    const int wm = wid >> 1, wn = wid & 1;
    const int g = lane >> 2, tg = lane & 3;

    stage_load(smc, 0, Ah, Al, Bh, Bl, arow, brow, 0, tid);
    asm volatile("cp.async.commit_group;\n" ::: "memory");

    for (int ch = 0; ch < 64; ch++) {
        __syncthreads();
        if (ch + 1 < 64) {
            stage_load(smc, (ch+1) & 1, Ah, Al, Bh, Bl, arow, brow, (ch+1)*32, tid);
            asm volatile("cp.async.commit_group;\n" ::: "memory");
            asm volatile("cp.async.wait_group 1;\n" ::: "memory");
        } else {
            asm volatile("cp.async.wait_group 0;\n" ::: "memory");
        }
        __syncthreads();

        const char* st = smc + (ch & 1)*STAGE_BYTES;
        const __nv_bfloat16* sAh = (const __nv_bfloat16*)(st);
        const __nv_bfloat16* sAl = (const __nv_bfloat16*)(st + TILE_B);
        const __nv_bfloat16* sBh = (const __nv_bfloat16*)(st + 2*TILE_B);
        const __nv_bfloat16* sBl = (const __nv_bfloat16*)(st + 3*TILE_B);

#pragma unroll
        for (int pass = 0; pass < 3; pass++) {
            const __nv_bfloat16* A_ = (pass == 2) ? sAl : sAh;
            const __nv_bfloat16* B_ = (pass == 1) ? sBl : sBh;
#pragma unroll
            for (int kk = 0; kk < 32; kk += 16) {
                uint32_t a[2][4], b[8][2];
#pragma unroll
                for (int mt = 0; mt < 2; mt++) {
                    const int r = wm*32 + mt*16 + g;
                    a[mt][0] = *(const uint32_t*)&A_[r*40     + kk + 2*tg];
                    a[mt][1] = *(const uint32_t*)&A_[(r+8)*40 + kk + 2*tg];
                    a[mt][2] = *(const uint32_t*)&A_[r*40     + kk + 2*tg + 8];
                    a[mt][3] = *(const uint32_t*)&A_[(r+8)*40 + kk + 2*tg + 8];
                }
#pragma unroll
                for (int nt = 0; nt < 8; nt++) {
                    const int r = wn*64 + nt*8 + g;
                    b[nt][0] = *(const uint32_t*)&B_[r*40 + kk + 2*tg];
                    b[nt][1] = *(const uint32_t*)&B_[r*40 + kk + 2*tg + 8];
                }
#pragma unroll
                for (int mt = 0; mt < 2; mt++)
#pragma unroll
                    for (int nt = 0; nt < 8; nt++)
                        mma16816(cacc[mt][nt], a[mt], b[nt]);
            }
        }
    }

    // accumulators -> smem epi buffer [128][132]
    __syncthreads();
    float* epi = (float*)smc;
#pragma unroll
    for (int mt = 0; mt < 2; mt++)
#pragma unroll
        for (int nt = 0; nt < 8; nt++) {
            const int r0 = wm*32 + mt*16 + g;
            const int c0 = wn*64 + nt*8 + 2*tg;
            *(float2*)&epi[r0*132 + c0]     = make_float2(cacc[mt][nt][0], cacc[mt][nt][1]);
            *(float2*)&epi[(r0+8)*132 + c0] = make_float2(cacc[mt][nt][2], cacc[mt][nt][3]);
        }
    __syncthreads();
}

// Merged Q/K/V projection GEMM: blockIdx.z selects weight + epilogue.
__global__ __launch_bounds__(256, 2) void gemm_qkv(const float* __restrict__ cosT,
                                                   const float* __restrict__ sinT)
{
    extern __shared__ char smc[];
    const int tid = threadIdx.x;
    const int bn = blockIdx.x, bm = blockIdx.y, sel = blockIdx.z;

    const __nv_bfloat16* Bh = (sel == 0) ? g_Wqh : (sel == 1) ? g_Wkh : g_Wvh;
    const __nv_bfloat16* Bl = (sel == 0) ? g_Wql : (sel == 1) ? g_Wkl : g_Wvl;

    float cacc[2][8][4];
#pragma unroll
    for (int mt = 0; mt < 2; mt++)
#pragma unroll
        for (int nt = 0; nt < 8; nt++)
#pragma unroll
            for (int q = 0; q < 4; q++) cacc[mt][nt][q] = 0.f;

    gemm_mainloop(smc, g_Xh, g_Xl, Bh, Bl, (size_t)bm*128, (size_t)bn*128, tid, cacc);

    float* epi = (float*)smc;
    if (sel <= 1) {
        __nv_bfloat16* Oh = (sel == 0) ? g_Qh : g_Kh;
        __nv_bfloat16* Ol = (sel == 0) ? g_Ql : g_Kl;
        for (int i = tid; i < 128*128; i += 256) {
            const int r = i >> 7, c = i & 127;
            const float v = epi[r*132 + c];
            const int m = bm*128 + r;
            const int b = m >> 11, s = m & 2047;
            const float cs = cosT[s*HDm + c];
            const float sn = sinT[s*HDm + c];
            const float o  = epi[r*132 + (c ^ 64)];
            const float res = (c < 64) ? (v*cs - o*sn) : (v*cs + o*sn);
            const size_t idx = ((size_t)(b*HH + bn)*SS + s)*HDm + c;
            const __nv_bfloat16 hh = __float2bfloat16(res);
            Oh[idx] = hh;
            Ol[idx] = __float2bfloat16(res - __bfloat162float(hh));
        }
    } else {
        const int b = (bm*128) >> 11;
        const int s0 = (bm*128) & 2047;
        for (int i = tid; i < 128*16; i += 256) {
            const int c  = i & 127;
            const int r0 = (i >> 7)*8;
            __nv_bfloat16 hbuf[8], lbuf[8];
#pragma unroll
            for (int j = 0; j < 8; j++) {
                const float v = epi[(r0+j)*132 + c];
                hbuf[j] = __float2bfloat16(v);
                lbuf[j] = __float2bfloat16(v - __bfloat162float(hbuf[j]));
            }
            const size_t dst = ((size_t)(b*HH + bn)*HDm + c)*SS + s0 + r0;
            *(uint4*)&g_VhT[dst] = *(uint4*)hbuf;
            *(uint4*)&g_VlT[dst] = *(uint4*)lbuf;
        }
    }
}

// Output GEMM: ctx @ Wo^T -> fp32 out
__global__ __launch_bounds__(256, 2) void gemm_out(float* __restrict__ outp)
{
    extern __shared__ char smc[];
    const int tid = threadIdx.x;
    const int bn = blockIdx.x, bm = blockIdx.y;

    float cacc[2][8][4];
#pragma unroll
    for (int mt = 0; mt < 2; mt++)
#pragma unroll
        for (int nt = 0; nt < 8; nt++)
#pragma unroll
            for (int q = 0; q < 4; q++) cacc[mt][nt][q] = 0.f;

    gemm_mainloop(smc, g_Ch, g_Cl, g_Woh, g_Wol, (size_t)bm*128, (size_t)bn*128, tid, cacc);

    float* epi = (float*)smc;
    for (int i = tid; i < 128*128; i += 256) {
        const int r = i >> 7, c = i & 127;
        outp[(size_t)(bm*128 + r)*DD + bn*128 + c] = epi[r*132 + c];
    }
}

// ---------------------------------------------------------------------------
// Flash attention, mma.sync bf16 3x-split. 256 threads (8 warps), 128 q rows
// per CTA, 64-row K/V tiles double-buffered. Heavy-first scheduling.
// Per-warp skip of fully-masked diagonal tiles.
// ---------------------------------------------------------------------------
#define QROWB 272
#define VROWB 144
#define OFF_QH 0
#define OFF_QL (128*QROWB)                 // 34816
#define STG0   (2*128*QROWB)               // 69632
#define SOFF_KH 0
#define SOFF_KL (64*QROWB)                 // 17408
#define SOFF_VH (2*64*QROWB)               // 34816
#define SOFF_VL (2*64*QROWB + 128*VROWB)   // 53248
#define STG_SZ  (2*64*QROWB + 2*128*VROWB) // 71680
#define FSMEM   (STG0 + 2*STG_SZ)          // 212992

__device__ __forceinline__ void load_kv(uint32_t sb, int stage,
                                        size_t qkb, size_t vb, int j0, int tid)
{
    const uint32_t base = sb + STG0 + stage*STG_SZ;
#pragma unroll
    for (int j = 0; j < 4; j++) {
        const int idx = j*256 + tid;
        const int row = idx >> 4, c16 = idx & 15;
        cpasync16(base + SOFF_KH + row*QROWB + c16*16, g_Kh + qkb + (size_t)(j0+row)*HDm + c16*8);
        cpasync16(base + SOFF_KL + row*QROWB + c16*16, g_Kl + qkb + (size_t)(j0+row)*HDm + c16*8);
        const int vrow = idx >> 3, c8 = idx & 7;
        cpasync16(base + SOFF_VH + vrow*VROWB + c8*16, g_VhT + vb + (size_t)vrow*SS + j0 + c8*8);
        cpasync16(base + SOFF_VL + vrow*VROWB + c8*16, g_VlT + vb + (size_t)vrow*SS + j0 + c8*8);
    }
}

__global__ __launch_bounds__(256) void flash_mma()
{
    extern __shared__ char fs[];
    const uint32_t sb = smem_u32(fs);
    const int tid = threadIdx.x, wid = tid >> 5, lane = tid & 31;
    const int gg = lane >> 2, tg = lane & 3;
    const int bh = blockIdx.y;
    const int q0 = (gridDim.x - 1 - blockIdx.x) * 128;   // heavy-first (LPT)
    const int wq = wid * 16;

    const size_t qkb = (size_t)bh * SS * HDm;   // [bh][s][d]
    const size_t vb  = (size_t)bh * HDm * SS;   // [bh][d][s]

    // load Q hi/lo (128 rows, once)
#pragma unroll
    for (int j = 0; j < 8; j++) {
        const int idx = j*256 + tid;
        const int row = idx >> 4, c16 = idx & 15;
        cpasync16(sb + OFF_QH + row*QROWB + c16*16, g_Qh + qkb + (size_t)(q0+row)*HDm + c16*8);
        cpasync16(sb + OFF_QL + row*QROWB + c16*16, g_Ql + qkb + (size_t)(q0+row)*HDm + c16*8);
    }
    asm volatile("cp.async.commit_group;\n" ::: "memory");

    const int ntiles = q0/64 + 2;
    load_kv(sb, 0, qkb, vb, 0, tid);
    asm volatile("cp.async.commit_group;\n" ::: "memory");

    float m2[2] = {-1e30f, -1e30f}, l2[2] = {0.f, 0.f};
    float oacc[16][4];
#pragma unroll
    for (int i = 0; i < 16; i++)
#pragma unroll
        for (int q = 0; q < 4; q++) oacc[i][q] = 0.f;

    const float scale = 0.08838834764831845f;
    const __nv_bfloat16* sQh = (const __nv_bfloat16*)(fs + OFF_QH);
    const __nv_bfloat16* sQl = (const __nv_bfloat16*)(fs + OFF_QL);

    for (int t = 0; t < ntiles; t++) {
        const int j0 = t * 64;
        if (t + 1 < ntiles) {
            load_kv(sb, (t+1) & 1, qkb, vb, (t+1)*64, tid);
            asm volatile("cp.async.commit_group;\n" ::: "memory");
            asm volatile("cp.async.wait_group 1;\n" ::: "memory");
        } else {
            asm volatile("cp.async.wait_group 0;\n" ::: "memory");
        }
        __syncthreads();

        // warp fully masked for this tile? (max row this warp owns = q0+wq+15)
        if (j0 <= q0 + wq + 15) {
            const char* stg = fs + STG0 + (t & 1)*STG_SZ;
            const __nv_bfloat16* sKh = (const __nv_bfloat16*)(stg + SOFF_KH);
            const __nv_bfloat16* sKl = (const __nv_bfloat16*)(stg + SOFF_KL);
            const __nv_bfloat16* sVh = (const __nv_bfloat16*)(stg + SOFF_VH);
            const __nv_bfloat16* sVl = (const __nv_bfloat16*)(stg + SOFF_VL);

            // ---- scores: S = Q K^T via 3 passes ----
            float sacc[8][4];
#pragma unroll
            for (int nt = 0; nt < 8; nt++)
#pragma unroll
                for (int q = 0; q < 4; q++) sacc[nt][q] = 0.f;

#pragma unroll
            for (int pass = 0; pass < 3; pass++) {
                const __nv_bfloat16* A_ = (pass == 2) ? sQl : sQh;
                const __nv_bfloat16* B_ = (pass == 1) ? sKl : sKh;
#pragma unroll
                for (int kk = 0; kk < 128; kk += 16) {
                    uint32_t a[4];
                    const int r = wq + gg;
                    a[0] = *(const uint32_t*)&A_[r*136     + kk + 2*tg];
                    a[1] = *(const uint32_t*)&A_[(r+8)*136 + kk + 2*tg];
                    a[2] = *(const uint32_t*)&A_[r*136     + kk + 2*tg + 8];
                    a[3] = *(const uint32_t*)&A_[(r+8)*136 + kk + 2*tg + 8];
#pragma unroll
                    for (int nt = 0; nt < 8; nt++) {
                        uint32_t b[2];
                        const int kr = nt*8 + gg;
                        b[0] = *(const uint32_t*)&B_[kr*136 + kk + 2*tg];
                        b[1] = *(const uint32_t*)&B_[kr*136 + kk + 2*tg + 8];
                        mma16816(sacc[nt], a, b);
                    }
                }
            }

            // ---- mask + online softmax (rows gg and gg+8) ----
            float corr[2];
#pragma unroll
            for (int h2 = 0; h2 < 2; h2++) {
                const int r = q0 + wq + gg + h2*8;
                float mx = -1e30f;
#pragma unroll
                for (int nt = 0; nt < 8; nt++)
#pragma unroll
                    for (int e = 0; e < 2; e++) {
                        const int col = j0 + nt*8 + 2*tg + e;
                        float v = (col <= r) ? sacc[nt][h2*2+e]*scale : -1e30f;
                        sacc[nt][h2*2+e] = v;
                        mx = fmaxf(mx, v);
                    }
                mx = fmaxf(mx, __shfl_xor_sync(0xffffffffu, mx, 1));
                mx = fmaxf(mx, __shfl_xor_sync(0xffffffffu, mx, 2));
                const float mn = fmaxf(m2[h2], mx);
                corr[h2] = __expf(m2[h2] - mn);
                m2[h2] = mn;
                float rs = 0.f;
#pragma unroll
                for (int nt = 0; nt < 8; nt++)
#pragma unroll
                    for (int e = 0; e < 2; e++) {
                        const float p = __expf(sacc[nt][h2*2+e] - mn);
                        sacc[nt][h2*2+e] = p;
                        rs += p;
                    }
                rs += __shfl_xor_sync(0xffffffffu, rs, 1);
                rs += __shfl_xor_sync(0xffffffffu, rs, 2);
                l2[h2] = l2[h2]*corr[h2] + rs;
            }
#pragma unroll
            for (int nt2 = 0; nt2 < 16; nt2++) {
                oacc[nt2][0] *= corr[0]; oacc[nt2][1] *= corr[0];
                oacc[nt2][2] *= corr[1]; oacc[nt2][3] *= corr[1];
            }

            // ---- pack P hi/lo into A fragments (register-only) ----
            uint32_t aPh[4][4], aPl[4][4];
#pragma unroll
            for (int jp = 0; jp < 4; jp++) {
#pragma unroll
                for (int f = 0; f < 4; f++) {
                    const int nt = 2*jp + (f >> 1);
                    const int e0 = (f & 1)*2;
                    const float p0 = sacc[nt][e0], p1 = sacc[nt][e0+1];
                    const __nv_bfloat16 h0 = __float2bfloat16(p0);
                    const __nv_bfloat16 h1 = __float2bfloat16(p1);
                    __nv_bfloat162 hp; hp.x = h0; hp.y = h1;
                    aPh[jp][f] = *(uint32_t*)&hp;
                    aPl[jp][f] = pack_bf2(p0 - __bfloat162float(h0), p1 - __bfloat162float(h1));
                }
            }

            // ---- PV: oacc += Ph Vh + Ph Vl + Pl Vh ----
#pragma unroll
            for (int jp = 0; jp < 4; jp++) {
#pragma unroll
                for (int nt2 = 0; nt2 < 16; nt2++) {
                    const int dr = nt2*8 + gg;
                    uint32_t bhf[2], blf[2];
                    bhf[0] = *(const uint32_t*)&sVh[dr*72 + jp*16 + 2*tg];
                    bhf[1] = *(const uint32_t*)&sVh[dr*72 + jp*16 + 2*tg + 8];
                    blf[0] = *(const uint32_t*)&sVl[dr*72 + jp*16 + 2*tg];
                    blf[1] = *(const uint32_t*)&sVl[dr*72 + jp*16 + 2*tg + 8];
                    mma16816(oacc[nt2], aPh[jp], bhf);
                    mma16816(oacc[nt2], aPh[jp], blf);
                    mma16816(oacc[nt2], aPl[jp], bhf);
                }
            }
        }
        __syncthreads();   // all warps done before next iter overwrites stage
    }

    // ---- epilogue: ctx bf16 hi/lo, [b, s, h*HD + d] ----
    const int b = bh / HH, h = bh % HH;
#pragma unroll
    for (int h2 = 0; h2 < 2; h2++) {
        const float inv = 1.f / l2[h2];
        const int r = q0 + wq + gg + h2*8;
        const size_t base = ((size_t)(b*SS + r))*DD + h*HDm;
#pragma unroll
        for (int nt2 = 0; nt2 < 16; nt2++) {
            const int d = nt2*8 + 2*tg;
            const float v0 = oacc[nt2][h2*2]   * inv;
            const float v1 = oacc[nt2][h2*2+1] * inv;
            const __nv_bfloat16 h0 = __float2bfloat16(v0);
            const __nv_bfloat16 h1 = __float2bfloat16(v1);
            __nv_bfloat162 hp; hp.x = h0; hp.y = h1;
            *(uint32_t*)&g_Ch[base + d] = *(uint32_t*)&hp;
            *(uint32_t*)&g_Cl[base + d] =
                pack_bf2(v0 - __bfloat162float(h0), v1 - __bfloat162float(h1));
        }
    }
}

// ---------------------------------------------------------------------------
extern "C" void kernel_launch(void* const* d_in, const int* in_sizes, int n_in,
                              void* d_out, int out_size)
{
    const float* x    = (const float*)d_in[0];
    const float* Wq   = (const float*)d_in[1];
    const float* Wk   = (const float*)d_in[2];
    const float* Wv   = (const float*)d_in[3];
    const float* Wo   = (const float*)d_in[4];
    const float* cosT = (const float*)d_in[5];
    const float* sinT = (const float*)d_in[6];
    float* out = (float*)d_out;

    cudaFuncSetAttribute(gemm_qkv, cudaFuncAttributeMaxDynamicSharedMemorySize, GSMEM_TOTAL);
    cudaFuncSetAttribute(gemm_out, cudaFuncAttributeMaxDynamicSharedMemorySize, GSMEM_TOTAL);
    cudaFuncSetAttribute(flash_mma, cudaFuncAttributeMaxDynamicSharedMemorySize, FSMEM);

    const int nx4 = MM * DD / 4;
    const int nw4 = DD * DD / 4;
    split_kernel<0><<<nx4 / 256, 256>>>(x,  nx4);
    split_kernel<1><<<nw4 / 256, 256>>>(Wq, nw4);
    split_kernel<2><<<nw4 / 256, 256>>>(Wk, nw4);
    split_kernel<3><<<nw4 / 256, 256>>>(Wv, nw4);
    split_kernel<4><<<nw4 / 256, 256>>>(Wo, nw4);

    gemm_qkv<<<dim3(DD/128, MM/128, 3), 256, GSMEM_TOTAL>>>(cosT, sinT);

    flash_mma<<<dim3(SS/128, Bb*HH), 256, FSMEM>>>();

    gemm_out<<<dim3(DD/128, MM/128), 256, GSMEM_TOTAL>>>(out);
}

// round 11
// speedup vs baseline: 3.4404x; 1.1310x over previous
#include <cuda_runtime.h>
#include <cuda_bf16.h>
#include <math.h>
#include <stdint.h>

#define Bb 2
#define SS 2048
#define DD 2048
#define HH 16
#define HDm 128
#define MM (Bb*SS)   // 4096

// ---------------------------------------------------------------------------
// Device-global scratch (no allocations allowed)
// ---------------------------------------------------------------------------
__device__ __align__(16) __nv_bfloat16 g_Xh[(size_t)MM*DD],  g_Xl[(size_t)MM*DD];
__device__ __align__(16) __nv_bfloat16 g_Wqh[(size_t)DD*DD], g_Wql[(size_t)DD*DD];
__device__ __align__(16) __nv_bfloat16 g_Wkh[(size_t)DD*DD], g_Wkl[(size_t)DD*DD];
__device__ __align__(16) __nv_bfloat16 g_Wvh[(size_t)DD*DD], g_Wvl[(size_t)DD*DD];
__device__ __align__(16) __nv_bfloat16 g_Woh[(size_t)DD*DD], g_Wol[(size_t)DD*DD];
__device__ __align__(16) __nv_bfloat16 g_Ch[(size_t)MM*DD],  g_Cl[(size_t)MM*DD];

// post-RoPE Q/K in bf16 hi/lo, [b,h,s,d]
__device__ __align__(16) __nv_bfloat16 g_Qh[(size_t)MM*DD], g_Ql[(size_t)MM*DD];
__device__ __align__(16) __nv_bfloat16 g_Kh[(size_t)MM*DD], g_Kl[(size_t)MM*DD];
// V transposed, [b,h,d,s], bf16 hi/lo
__device__ __align__(16) __nv_bfloat16 g_VhT[(size_t)MM*DD], g_VlT[(size_t)MM*DD];

// ---------------------------------------------------------------------------
// helpers (arch-portable PTX only)
// ---------------------------------------------------------------------------
__device__ __forceinline__ uint32_t smem_u32(const void* p) {
    uint32_t a;
    asm("{ .reg .u64 t; cvta.to.shared.u64 t, %1; cvt.u32.u64 %0, t; }"
        : "=r"(a) : "l"(p));
    return a;
}

__device__ __forceinline__ void mma16816(float* c, const uint32_t* a, const uint32_t* b) {
    asm volatile(
        "mma.sync.aligned.m16n8k16.row.col.f32.bf16.bf16.f32 "
        "{%0,%1,%2,%3}, {%4,%5,%6,%7}, {%8,%9}, {%0,%1,%2,%3};"
        : "+f"(c[0]), "+f"(c[1]), "+f"(c[2]), "+f"(c[3])
        : "r"(a[0]), "r"(a[1]), "r"(a[2]), "r"(a[3]), "r"(b[0]), "r"(b[1]));
}

__device__ __forceinline__ void ldsm4(uint32_t* r, uint32_t addr) {
    asm volatile("ldmatrix.sync.aligned.m8n8.x4.shared.b16 {%0,%1,%2,%3}, [%4];"
        : "=r"(r[0]), "=r"(r[1]), "=r"(r[2]), "=r"(r[3]) : "r"(addr));
}

__device__ __forceinline__ void cpasync16(uint32_t dst, const void* src) {
    asm volatile("cp.async.cg.shared.global [%0], [%1], 16;\n" :: "r"(dst), "l"(src) : "memory");
}

__device__ __forceinline__ uint32_t pack_bf2(float a, float b) {
    __nv_bfloat162 t;
    t.x = __float2bfloat16(a);
    t.y = __float2bfloat16(b);
    return *(uint32_t*)&t;
}

// ---------------------------------------------------------------------------
// fp32 -> bf16 hi/lo splitter
// ---------------------------------------------------------------------------
template<int SEL>
__global__ __launch_bounds__(256) void split_kernel(const float* __restrict__ src, int n4)
{
    const int i = blockIdx.x * 256 + threadIdx.x;
    if (i >= n4) return;
    __nv_bfloat16* hi = (SEL==0) ? g_Xh : (SEL==1) ? g_Wqh : (SEL==2) ? g_Wkh
                      : (SEL==3) ? g_Wvh : g_Woh;
    __nv_bfloat16* lo = (SEL==0) ? g_Xl : (SEL==1) ? g_Wql : (SEL==2) ? g_Wkl
                      : (SEL==3) ? g_Wvl : g_Wol;
    const float4 v = ((const float4*)src)[i];
    __nv_bfloat162 h0, h1, l0, l1;
    h0.x = __float2bfloat16(v.x); h0.y = __float2bfloat16(v.y);
    h1.x = __float2bfloat16(v.z); h1.y = __float2bfloat16(v.w);
    l0.x = __float2bfloat16(v.x - __bfloat162float(h0.x));
    l0.y = __float2bfloat16(v.y - __bfloat162float(h0.y));
    l1.x = __float2bfloat16(v.z - __bfloat162float(h1.x));
    l1.y = __float2bfloat16(v.w - __bfloat162float(h1.y));
    ((__nv_bfloat162*)hi)[i*2]   = h0;
    ((__nv_bfloat162*)hi)[i*2+1] = h1;
    ((__nv_bfloat162*)lo)[i*2]   = l0;
    ((__nv_bfloat162*)lo)[i*2+1] = l1;
}

// ---------------------------------------------------------------------------
// HMMA GEMM mainloop. 128x128 tile, BK=32, 256 threads, 2-stage cp.async.
// Fragments via ldmatrix.x4; A kept resident, B streamed, hi/lo loaded once
// per k-step and reused across the 3 split passes.
// ---------------------------------------------------------------------------
#define TILE_B 10240
#define STAGE_BYTES (4*TILE_B)
#define GSMEM_TOTAL (2*STAGE_BYTES)

__device__ __forceinline__ void stage_load(char* smc, int stage,
    const __nv_bfloat16* Ah, const __nv_bfloat16* Al,
    const __nv_bfloat16* Bh, const __nv_bfloat16* Bl,
    size_t arow, size_t brow, int k0, int tid)
{
    const __nv_bfloat16* srcs[4] = {Ah, Al, Bh, Bl};
#pragma unroll
    for (int t = 0; t < 4; t++) {
        const size_t rb = (t < 2) ? arow : brow;
        const __nv_bfloat16* s = srcs[t];
        char* base = smc + stage*STAGE_BYTES + t*TILE_B;
#pragma unroll
        for (int h = 0; h < 2; h++) {
            const int c = tid + h*256;
            const int row = c >> 2, col = c & 3;
            cpasync16(smem_u32(base + row*80 + col*16), s + (rb + row)*(size_t)DD + k0 + col*8);
        }
    }
}

__device__ __forceinline__ void gemm_mainloop(char* smc,
    const __nv_bfloat16* Ah, const __nv_bfloat16* Al,
    const __nv_bfloat16* Bh, const __nv_bfloat16* Bl,
    size_t arow, size_t brow, int tid, float cacc[2][8][4])
{
    const int wid = tid >> 5, lane = tid & 31;
    const int wm = wid >> 1, wn = wid & 1;
    const int g = lane >> 2, tg = lane & 3;

    // ldmatrix lane addressing
    const int rowA = (lane & 7) + ((lane >> 3) & 1) * 8;
    const int khA  = lane >> 4;
    const int rowB = ((lane >> 4) & 1) * 8 + (lane & 7);
    const int khB  = (lane >> 3) & 1;

    const uint32_t sb = smem_u32(smc);
    const uint32_t aoff = (uint32_t)((wm*32 + rowA)*80 + khA*16);
    const uint32_t boff = (uint32_t)((wn*64 + rowB)*80 + khB*16);

    stage_load(smc, 0, Ah, Al, Bh, Bl, arow, brow, 0, tid);
    asm volatile("cp.async.commit_group;\n" ::: "memory");

    for (int ch = 0; ch < 64; ch++) {
        __syncthreads();
        if (ch + 1 < 64) {
            stage_load(smc, (ch+1) & 1, Ah, Al, Bh, Bl, arow, brow, (ch+1)*32, tid);
            asm volatile("cp.async.commit_group;\n" ::: "memory");
            asm volatile("cp.async.wait_group 1;\n" ::: "memory");
        } else {
            asm volatile("cp.async.wait_group 0;\n" ::: "memory");
        }
        __syncthreads();

        const uint32_t st = sb + (ch & 1)*STAGE_BYTES;
#pragma unroll
        for (int kk2 = 0; kk2 < 2; kk2++) {
            const uint32_t kb = kk2*32;
            uint32_t ah[2][4], al[2][4];
            ldsm4(ah[0], st + aoff + kb);
            ldsm4(ah[1], st + aoff + 16*80 + kb);
            ldsm4(al[0], st + TILE_B + aoff + kb);
            ldsm4(al[1], st + TILE_B + aoff + 16*80 + kb);
#pragma unroll
            for (int p = 0; p < 4; p++) {
                uint32_t bhf[4], blf[4];
                ldsm4(bhf, st + 2*TILE_B + boff + p*(16*80) + kb);
                ldsm4(blf, st + 3*TILE_B + boff + p*(16*80) + kb);
#pragma unroll
                for (int mt = 0; mt < 2; mt++) {
                    mma16816(cacc[mt][2*p],   ah[mt], bhf);
                    mma16816(cacc[mt][2*p+1], ah[mt], bhf+2);
                    mma16816(cacc[mt][2*p],   ah[mt], blf);
                    mma16816(cacc[mt][2*p+1], ah[mt], blf+2);
                    mma16816(cacc[mt][2*p],   al[mt], bhf);
                    mma16816(cacc[mt][2*p+1], al[mt], bhf+2);
                }
            }
        }
    }

    // accumulators -> smem epi buffer [128][132]
    __syncthreads();
    float* epi = (float*)smc;
#pragma unroll
    for (int mt = 0; mt < 2; mt++)
#pragma unroll
        for (int nt = 0; nt < 8; nt++) {
            const int r0 = wm*32 + mt*16 + g;
            const int c0 = wn*64 + nt*8 + 2*tg;
            *(float2*)&epi[r0*132 + c0]     = make_float2(cacc[mt][nt][0], cacc[mt][nt][1]);
            *(float2*)&epi[(r0+8)*132 + c0] = make_float2(cacc[mt][nt][2], cacc[mt][nt][3]);
        }
    __syncthreads();
}

// Merged Q/K/V projection GEMM: blockIdx.z selects weight + epilogue.
__global__ __launch_bounds__(256, 2) void gemm_qkv(const float* __restrict__ cosT,
                                                   const float* __restrict__ sinT)
{
    extern __shared__ char smc[];
    const int tid = threadIdx.x;
    const int bn = blockIdx.x, bm = blockIdx.y, sel = blockIdx.z;

    const __nv_bfloat16* Bh = (sel == 0) ? g_Wqh : (sel == 1) ? g_Wkh : g_Wvh;
    const __nv_bfloat16* Bl = (sel == 0) ? g_Wql : (sel == 1) ? g_Wkl : g_Wvl;

    float cacc[2][8][4];
#pragma unroll
    for (int mt = 0; mt < 2; mt++)
#pragma unroll
        for (int nt = 0; nt < 8; nt++)
#pragma unroll
            for (int q = 0; q < 4; q++) cacc[mt][nt][q] = 0.f;

    gemm_mainloop(smc, g_Xh, g_Xl, Bh, Bl, (size_t)bm*128, (size_t)bn*128, tid, cacc);

    float* epi = (float*)smc;
    if (sel <= 1) {
        __nv_bfloat16* Oh = (sel == 0) ? g_Qh : g_Kh;
        __nv_bfloat16* Ol = (sel == 0) ? g_Ql : g_Kl;
        for (int i = tid; i < 128*128; i += 256) {
            const int r = i >> 7, c = i & 127;
            const float v = epi[r*132 + c];
            const int m = bm*128 + r;
            const int b = m >> 11, s = m & 2047;
            const float cs = cosT[s*HDm + c];
            const float sn = sinT[s*HDm + c];
            const float o  = epi[r*132 + (c ^ 64)];
            const float res = (c < 64) ? (v*cs - o*sn) : (v*cs + o*sn);
            const size_t idx = ((size_t)(b*HH + bn)*SS + s)*HDm + c;
            const __nv_bfloat16 hh = __float2bfloat16(res);
            Oh[idx] = hh;
            Ol[idx] = __float2bfloat16(res - __bfloat162float(hh));
        }
    } else {
        const int b = (bm*128) >> 11;
        const int s0 = (bm*128) & 2047;
        for (int i = tid; i < 128*16; i += 256) {
            const int c  = i & 127;
            const int r0 = (i >> 7)*8;
            __nv_bfloat16 hbuf[8], lbuf[8];
#pragma unroll
            for (int j = 0; j < 8; j++) {
                const float v = epi[(r0+j)*132 + c];
                hbuf[j] = __float2bfloat16(v);
                lbuf[j] = __float2bfloat16(v - __bfloat162float(hbuf[j]));
            }
            const size_t dst = ((size_t)(b*HH + bn)*HDm + c)*SS + s0 + r0;
            *(uint4*)&g_VhT[dst] = *(uint4*)hbuf;
            *(uint4*)&g_VlT[dst] = *(uint4*)lbuf;
        }
    }
}

// Output GEMM: ctx @ Wo^T -> fp32 out
__global__ __launch_bounds__(256, 2) void gemm_out(float* __restrict__ outp)
{
    extern __shared__ char smc[];
    const int tid = threadIdx.x;
    const int bn = blockIdx.x, bm = blockIdx.y;

    float cacc[2][8][4];
#pragma unroll
    for (int mt = 0; mt < 2; mt++)
#pragma unroll
        for (int nt = 0; nt < 8; nt++)
#pragma unroll
            for (int q = 0; q < 4; q++) cacc[mt][nt][q] = 0.f;

    gemm_mainloop(smc, g_Ch, g_Cl, g_Woh, g_Wol, (size_t)bm*128, (size_t)bn*128, tid, cacc);

    float* epi = (float*)smc;
    for (int i = tid; i < 128*128; i += 256) {
        const int r = i >> 7, c = i & 127;
        outp[(size_t)(bm*128 + r)*DD + bn*128 + c] = epi[r*132 + c];
    }
}

// ---------------------------------------------------------------------------
// Flash attention, mma.sync bf16 3x-split, ldmatrix fragments.
// 256 threads (8 warps), 128 q rows/CTA, 64-row K/V tiles double-buffered.
// ---------------------------------------------------------------------------
#define QROWB 272
#define VROWB 144
#define OFF_QH 0
#define OFF_QL (128*QROWB)                 // 34816
#define STG0   (2*128*QROWB)               // 69632
#define SOFF_KH 0
#define SOFF_KL (64*QROWB)                 // 17408
#define SOFF_VH (2*64*QROWB)               // 34816
#define SOFF_VL (2*64*QROWB + 128*VROWB)   // 53248
#define STG_SZ  (2*64*QROWB + 2*128*VROWB) // 71680
#define FSMEM   (STG0 + 2*STG_SZ)          // 212992

__device__ __forceinline__ void load_kv(uint32_t sb, int stage,
                                        size_t qkb, size_t vb, int j0, int tid)
{
    const uint32_t base = sb + STG0 + stage*STG_SZ;
#pragma unroll
    for (int j = 0; j < 4; j++) {
        const int idx = j*256 + tid;
        const int row = idx >> 4, c16 = idx & 15;
        cpasync16(base + SOFF_KH + row*QROWB + c16*16, g_Kh + qkb + (size_t)(j0+row)*HDm + c16*8);
        cpasync16(base + SOFF_KL + row*QROWB + c16*16, g_Kl + qkb + (size_t)(j0+row)*HDm + c16*8);
        const int vrow = idx >> 3, c8 = idx & 7;
        cpasync16(base + SOFF_VH + vrow*VROWB + c8*16, g_VhT + vb + (size_t)vrow*SS + j0 + c8*8);
        cpasync16(base + SOFF_VL + vrow*VROWB + c8*16, g_VlT + vb + (size_t)vrow*SS + j0 + c8*8);
    }
}

__global__ __launch_bounds__(256) void flash_mma()
{
    extern __shared__ char fs[];
    const uint32_t sb = smem_u32(fs);
    const int tid = threadIdx.x, wid = tid >> 5, lane = tid & 31;
    const int gg = lane >> 2, tg = lane & 3;
    const int bh = blockIdx.y;
    const int q0 = (gridDim.x - 1 - blockIdx.x) * 128;   // heavy-first (LPT)
    const int wq = wid * 16;

    // ldmatrix lane addressing
    const int rowA = (lane & 7) + ((lane >> 3) & 1) * 8;
    const int khA  = lane >> 4;
    const int rowB = ((lane >> 4) & 1) * 8 + (lane & 7);
    const int khB  = (lane >> 3) & 1;
    const uint32_t qfoff = (uint32_t)((wq + rowA)*QROWB + khA*16);
    const uint32_t kfoff = (uint32_t)(rowB*QROWB + khB*16);
    const uint32_t vfoff = (uint32_t)(rowB*VROWB + khB*16);

    const size_t qkb = (size_t)bh * SS * HDm;   // [bh][s][d]
    const size_t vb  = (size_t)bh * HDm * SS;   // [bh][d][s]

    // load Q hi/lo (128 rows, once)
#pragma unroll
    for (int j = 0; j < 8; j++) {
        const int idx = j*256 + tid;
        const int row = idx >> 4, c16 = idx & 15;
        cpasync16(sb + OFF_QH + row*QROWB + c16*16, g_Qh + qkb + (size_t)(q0+row)*HDm + c16*8);
        cpasync16(sb + OFF_QL + row*QROWB + c16*16, g_Ql + qkb + (size_t)(q0+row)*HDm + c16*8);
    }
    asm volatile("cp.async.commit_group;\n" ::: "memory");

    const int ntiles = q0/64 + 2;
    load_kv(sb, 0, qkb, vb, 0, tid);
    asm volatile("cp.async.commit_group;\n" ::: "memory");

    float m2[2] = {-1e30f, -1e30f}, l2[2] = {0.f, 0.f};
    float oacc[16][4];
#pragma unroll
    for (int i = 0; i < 16; i++)
#pragma unroll
        for (int q = 0; q < 4; q++) oacc[i][q] = 0.f;

    const float scale = 0.08838834764831845f;

    for (int t = 0; t < ntiles; t++) {
        const int j0 = t * 64;
        if (t + 1 < ntiles) {
            load_kv(sb, (t+1) & 1, qkb, vb, (t+1)*64, tid);
            asm volatile("cp.async.commit_group;\n" ::: "memory");
            asm volatile("cp.async.wait_group 1;\n" ::: "memory");
        } else {
            asm volatile("cp.async.wait_group 0;\n" ::: "memory");
        }
        __syncthreads();

        if (j0 <= q0 + wq + 15) {   // warp not fully masked
            const uint32_t stg = sb + STG0 + (t & 1)*STG_SZ;
            const uint32_t kH = stg + SOFF_KH + kfoff;
            const uint32_t kL = stg + SOFF_KL + kfoff;
            const uint32_t vH = stg + SOFF_VH + vfoff;
            const uint32_t vL = stg + SOFF_VL + vfoff;
            const uint32_t qH = sb + OFF_QH + qfoff;
            const uint32_t qL = sb + OFF_QL + qfoff;

            // ---- scores: S = Qh Kh + Qh Kl + Ql Kh ----
            float sacc[8][4];
#pragma unroll
            for (int nt = 0; nt < 8; nt++)
#pragma unroll
                for (int q = 0; q < 4; q++) sacc[nt][q] = 0.f;

#pragma unroll
            for (int kk2 = 0; kk2 < 8; kk2++) {
                const uint32_t kb = kk2*32;
                uint32_t qh[4], ql[4];
                ldsm4(qh, qH + kb);
                ldsm4(ql, qL + kb);
#pragma unroll
                for (int p = 0; p < 4; p++) {
                    uint32_t kh4[4], kl4[4];
                    ldsm4(kh4, kH + p*(16*QROWB) + kb);
                    ldsm4(kl4, kL + p*(16*QROWB) + kb);
                    mma16816(sacc[2*p],   qh, kh4);
                    mma16816(sacc[2*p+1], qh, kh4+2);
                    mma16816(sacc[2*p],   qh, kl4);
                    mma16816(sacc[2*p+1], qh, kl4+2);
                    mma16816(sacc[2*p],   ql, kh4);
                    mma16816(sacc[2*p+1], ql, kh4+2);
                }
            }

            // ---- mask + online softmax (rows gg and gg+8) ----
            float corr[2];
#pragma unroll
            for (int h2 = 0; h2 < 2; h2++) {
                const int r = q0 + wq + gg + h2*8;
                float mx = -1e30f;
#pragma unroll
                for (int nt = 0; nt < 8; nt++)
#pragma unroll
                    for (int e = 0; e < 2; e++) {
                        const int col = j0 + nt*8 + 2*tg + e;
                        float v = (col <= r) ? sacc[nt][h2*2+e]*scale : -1e30f;
                        sacc[nt][h2*2+e] = v;
                        mx = fmaxf(mx, v);
                    }
                mx = fmaxf(mx, __shfl_xor_sync(0xffffffffu, mx, 1));
                mx = fmaxf(mx, __shfl_xor_sync(0xffffffffu, mx, 2));
                const float mn = fmaxf(m2[h2], mx);
                corr[h2] = __expf(m2[h2] - mn);
                m2[h2] = mn;
                float rs = 0.f;
#pragma unroll
                for (int nt = 0; nt < 8; nt++)
#pragma unroll
                    for (int e = 0; e < 2; e++) {
                        const float p = __expf(sacc[nt][h2*2+e] - mn);
                        sacc[nt][h2*2+e] = p;
                        rs += p;
                    }
                rs += __shfl_xor_sync(0xffffffffu, rs, 1);
                rs += __shfl_xor_sync(0xffffffffu, rs, 2);
                l2[h2] = l2[h2]*corr[h2] + rs;
            }
#pragma unroll
            for (int nt2 = 0; nt2 < 16; nt2++) {
                oacc[nt2][0] *= corr[0]; oacc[nt2][1] *= corr[0];
                oacc[nt2][2] *= corr[1]; oacc[nt2][3] *= corr[1];
            }

            // ---- pack P hi/lo into A fragments (register-only) ----
            uint32_t aPh[4][4], aPl[4][4];
#pragma unroll
            for (int jp = 0; jp < 4; jp++) {
#pragma unroll
                for (int f = 0; f < 4; f++) {
                    const int nt = 2*jp + (f >> 1);
                    const int e0 = (f & 1)*2;
                    const float p0 = sacc[nt][e0], p1 = sacc[nt][e0+1];
                    const __nv_bfloat16 h0 = __float2bfloat16(p0);
                    const __nv_bfloat16 h1 = __float2bfloat16(p1);
                    __nv_bfloat162 hp; hp.x = h0; hp.y = h1;
                    aPh[jp][f] = *(uint32_t*)&hp;
                    aPl[jp][f] = pack_bf2(p0 - __bfloat162float(h0), p1 - __bfloat162float(h1));
                }
            }

            // ---- PV: oacc += Ph Vh + Ph Vl + Pl Vh ----
#pragma unroll
            for (int jp = 0; jp < 4; jp++) {
#pragma unroll
                for (int p = 0; p < 8; p++) {
                    uint32_t vh4[4], vl4[4];
                    ldsm4(vh4, vH + p*(16*VROWB) + jp*32);
                    ldsm4(vl4, vL + p*(16*VROWB) + jp*32);
                    mma16816(oacc[2*p],   aPh[jp], vh4);
                    mma16816(oacc[2*p+1], aPh[jp], vh4+2);
                    mma16816(oacc[2*p],   aPh[jp], vl4);
                    mma16816(oacc[2*p+1], aPh[jp], vl4+2);
                    mma16816(oacc[2*p],   aPl[jp], vh4);
                    mma16816(oacc[2*p+1], aPl[jp], vh4+2);
                }
            }
        }
        __syncthreads();   // all warps done before next iter overwrites stage
    }

    // ---- epilogue: ctx bf16 hi/lo, [b, s, h*HD + d] ----
    const int b = bh / HH, h = bh % HH;
#pragma unroll
    for (int h2 = 0; h2 < 2; h2++) {
        const float inv = 1.f / l2[h2];
        const int r = q0 + wq + gg + h2*8;
        const size_t base = ((size_t)(b*SS + r))*DD + h*HDm;
#pragma unroll
        for (int nt2 = 0; nt2 < 16; nt2++) {
            const int d = nt2*8 + 2*tg;
            const float v0 = oacc[nt2][h2*2]   * inv;
            const float v1 = oacc[nt2][h2*2+1] * inv;
            const __nv_bfloat16 h0 = __float2bfloat16(v0);
            const __nv_bfloat16 h1 = __float2bfloat16(v1);
            __nv_bfloat162 hp; hp.x = h0; hp.y = h1;
            *(uint32_t*)&g_Ch[base + d] = *(uint32_t*)&hp;
            *(uint32_t*)&g_Cl[base + d] =
                pack_bf2(v0 - __bfloat162float(h0), v1 - __bfloat162float(h1));
        }
    }
}

// ---------------------------------------------------------------------------
extern "C" void kernel_launch(void* const* d_in, const int* in_sizes, int n_in,
                              void* d_out, int out_size)
{
    const float* x    = (const float*)d_in[0];
    const float* Wq   = (const float*)d_in[1];
    const float* Wk   = (const float*)d_in[2];
    const float* Wv   = (const float*)d_in[3];
    const float* Wo   = (const float*)d_in[4];
    const float* cosT = (const float*)d_in[5];
    const float* sinT = (const float*)d_in[6];
    float* out = (float*)d_out;

    cudaFuncSetAttribute(gemm_qkv, cudaFuncAttributeMaxDynamicSharedMemorySize, GSMEM_TOTAL);
    cudaFuncSetAttribute(gemm_out, cudaFuncAttributeMaxDynamicSharedMemorySize, GSMEM_TOTAL);
    cudaFuncSetAttribute(flash_mma, cudaFuncAttributeMaxDynamicSharedMemorySize, FSMEM);

    const int nx4 = MM * DD / 4;
    const int nw4 = DD * DD / 4;
    split_kernel<0><<<nx4 / 256, 256>>>(x,  nx4);
    split_kernel<1><<<nw4 / 256, 256>>>(Wq, nw4);
    split_kernel<2><<<nw4 / 256, 256>>>(Wk, nw4);
    split_kernel<3><<<nw4 / 256, 256>>>(Wv, nw4);
    split_kernel<4><<<nw4 / 256, 256>>>(Wo, nw4);

    gemm_qkv<<<dim3(DD/128, MM/128, 3), 256, GSMEM_TOTAL>>>(cosT, sinT);

    flash_mma<<<dim3(SS/128, Bb*HH), 256, FSMEM>>>();

    gemm_out<<<dim3(DD/128, MM/128), 256, GSMEM_TOTAL>>>(out);
}